// round 15
// baseline (speedup 1.0000x reference)
#include <cuda_runtime.h>
#include <cuda_fp16.h>
#include <cstdint>
#include <math.h>

// ---------------------------------------------------------------------------
// SanaBlock: LN+adaLN -> LiteLA -> cross-attn -> GLUMBConv, B=2,N=4096,C=1152
// R15: vk_kernel 352-thread exact work split; scores skips pad stores.
//      GEMM core (BK templated, fused vt, merged prologue) as R14.
// ---------------------------------------------------------------------------
constexpr int Bb   = 2;
constexpr int Nn   = 4096;
constexpr int Cc   = 1152;
constexpr int Mkv  = 300;
constexpr int HIDd = 2880;
constexpr int HLA  = 36;
constexpr int HX   = 16;
constexpr int SLD  = 320;

__device__ __align__(256) float  g_big [47185920];
__device__ __align__(256) __half g_shh [(size_t)Bb * Nn * Cc];
__device__ __align__(256) float  g_x1  [(size_t)Bb * Nn * Cc];
__device__ __align__(256) __half g_x1h [(size_t)Bb * Nn * Cc];
__device__ __align__(256) float  g_x2  [(size_t)Bb * Nn * Cc];
__device__ __align__(256) __half g_glu [(size_t)Bb * Nn * HIDd];
__device__ __align__(256) __half g_kvb [(size_t)Bb * Mkv * 2 * Cc];
__device__ __align__(256) __half g_vt  [(size_t)Bb * HX * 72 * SLD];
__device__ __align__(256) __half g_prb [(size_t)Bb * HX * Nn * SLD];
__device__ __align__(256) __half g_yh  [(size_t)Bb * Mkv * Cc];
__device__ __align__(256) __half g_wts [20570112];
__device__ float g_vk [Bb * HLA * 33 * 32];   // transposed: [bh][d:32][e:33]
__device__ float g_mb [Bb * 6 * Cc];

constexpr size_t W_QKV = 0;
constexpr size_t W_APR = W_QKV + (size_t)3 * Cc * Cc;
constexpr size_t W_Q   = W_APR + (size_t)Cc * Cc;
constexpr size_t W_KV  = W_Q   + (size_t)Cc * Cc;
constexpr size_t W_CPR = W_KV  + (size_t)2 * Cc * Cc;
constexpr size_t W_INV = W_CPR + (size_t)Cc * Cc;
constexpr size_t W_PW  = W_INV + (size_t)2 * HIDd * Cc;

// ---------------------------------------------------------------------------
// FMA-only transcendentals
// ---------------------------------------------------------------------------
__device__ __forceinline__ float fexp(float t){
    t = fminf(fmaxf(t, -87.0f), 87.0f);
    float z = t * 1.4426950408889634f;
    float n = floorf(z);
    float f = z - n;
    float p = 1.5403530e-4f;
    p = fmaf(p, f, 1.3333558e-3f);
    p = fmaf(p, f, 9.6181291e-3f);
    p = fmaf(p, f, 5.5504109e-2f);
    p = fmaf(p, f, 2.4022651e-1f);
    p = fmaf(p, f, 6.9314718e-1f);
    p = fmaf(p, f, 1.0f);
    int i = (int)n;
    return p * __int_as_float((i + 127) << 23);
}
__device__ __forceinline__ float fsigmoid(float x){
    float u = fexp(-fabsf(x));
    float z = 1.0f + u;                    // [1,2]
    float y = fmaf(-0.47058824f, z, 1.4117647f);
    y = y * fmaf(-z, y, 2.0f);
    y = y * fmaf(-z, y, 2.0f);
    return (x >= 0.f) ? y : 1.0f - y;
}
__device__ __forceinline__ float fsilu(float x){ return x * fsigmoid(x); }

// ---------------------------------------------------------------------------
// helpers
// ---------------------------------------------------------------------------
__device__ __forceinline__ uint32_t smem_u32(const void* p){
    uint32_t a;
    asm("{ .reg .u64 t; cvta.to.shared.u64 t, %1; cvt.u32.u64 %0, t; }"
        : "=r"(a) : "l"(p));
    return a;
}
__device__ __forceinline__ void cp16(uint32_t dst, const void* src, int srcsz){
    asm volatile("cp.async.cg.shared.global [%0], [%1], 16, %2;"
        ::"r"(dst),"l"(src),"r"(srcsz):"memory");
}
#define CP_COMMIT() asm volatile("cp.async.commit_group;":::"memory")
#define CP_WAIT1()  asm volatile("cp.async.wait_group 1;":::"memory")

__device__ __forceinline__ void mma16(float* d, const uint32_t* a, const uint32_t* b){
    asm volatile("mma.sync.aligned.m16n8k16.row.col.f32.f16.f16.f32 "
        "{%0,%1,%2,%3},{%4,%5,%6,%7},{%8,%9},{%0,%1,%2,%3};"
        : "+f"(d[0]),"+f"(d[1]),"+f"(d[2]),"+f"(d[3])
        : "r"(a[0]),"r"(a[1]),"r"(a[2]),"r"(a[3]),"r"(b[0]),"r"(b[1]));
}
__device__ __forceinline__ void ldsm4(uint32_t& r0, uint32_t& r1, uint32_t& r2,
                                      uint32_t& r3, uint32_t addr){
    asm volatile("ldmatrix.sync.aligned.m8n8.x4.shared.b16 {%0,%1,%2,%3}, [%4];"
        : "=r"(r0),"=r"(r1),"=r"(r2),"=r"(r3) : "r"(addr));
}

// ---------------------------------------------------------------------------
// fp16 mma NT GEMM, BK templated (32 or 64): 3-stage cp.async, 1 barrier/tile.
// CTA 128x128, 8 warps (4M x 2N), warp tile 32x64, ldmatrix.x4 fragments.
// VT: scatter v-half of kv output into g_vt (transposed, padded).
// ---------------------------------------------------------------------------
template<int BK> struct GK {
    static constexpr int LDPH    = BK + 8;
    static constexpr int TILE_H  = 128 * LDPH;
    static constexpr int STAGE_H = 2 * TILE_H;
    static constexpr int SMEM    = 3 * STAGE_H * 2;
};
constexpr int MM_SMEM64 = GK<64>::SMEM;   // 110592
constexpr int MM_SMEM32 = GK<32>::SMEM;   // 61440

template<bool BIAS, int EPI, bool WF, bool WH, int BK, bool VT>
__global__ __launch_bounds__(256, 2)
void mma_gemm(const __half* A, const __half* Bw, const float* bias,
              const float* res, const float* gate,
              float* Of, __half* Oh, __half* vtout,
              int Mrows, int NloadB, int Nstore, int K,
              int lda, int ldb, int ldo,
              int HB, long aBs, long aHs, long bBs, long bHs, long oBs, long oHs,
              int gateStride)
{
    constexpr int LDPH    = GK<BK>::LDPH;
    constexpr int TILE_H  = GK<BK>::TILE_H;
    constexpr int STAGE_H = GK<BK>::STAGE_H;
    constexpr int CPR     = BK / 8;
    constexpr int LITER   = BK / 16;

    extern __shared__ __half smh[];
    uint32_t sbase = smem_u32(smh);
    int tid = threadIdx.x, wid = tid >> 5, lane = tid & 31;
    int warpM = wid >> 1, warpN = wid & 1;
    int m0 = blockIdx.y * 128, n0 = blockIdx.x * 128;

    if (gridDim.z > 1) {
        int z = blockIdx.z;
        int bI = z / HB, hI = z % HB;
        A  += bI * aBs + hI * aHs;
        Bw += bI * bBs + hI * bHs;
        if (WF) Of += bI * oBs + hI * oHs;
        if (WH) Oh += bI * oBs + hI * oHs;
    }

    const int T = (K + BK - 1) / BK;

    auto load_tile = [&](int t, int buf) {
        uint32_t base = sbase + (uint32_t)buf * STAGE_H * 2;
        int k0 = t * BK;
        #pragma unroll
        for (int i = 0; i < LITER; i++) {
            int c = tid + (i << 8);
            int row = c / CPR, ch = c % CPR;
            int gk = k0 + ch * 8;
            uint32_t dst = base + (uint32_t)(row * LDPH + ch * 8) * 2;
            const __half* ga = A + (size_t)(m0 + row) * lda + gk;
            cp16(dst, ga, ((m0 + row) < Mrows && gk < K) ? 16 : 0);
        }
        #pragma unroll
        for (int i = 0; i < LITER; i++) {
            int c = tid + (i << 8);
            int row = c / CPR, ch = c % CPR;
            int gk = k0 + ch * 8;
            uint32_t dst = base + (uint32_t)(TILE_H + row * LDPH + ch * 8) * 2;
            const __half* gb = Bw + (size_t)(n0 + row) * ldb + gk;
            cp16(dst, gb, ((n0 + row) < NloadB && gk < K) ? 16 : 0);
        }
    };

    float acc[2][8][4];
    #pragma unroll
    for (int mt = 0; mt < 2; mt++)
        #pragma unroll
        for (int nt = 0; nt < 8; nt++)
            #pragma unroll
            for (int q = 0; q < 4; q++) acc[mt][nt][q] = 0.f;

    load_tile(0, 0); CP_COMMIT();
    load_tile(1, 1); CP_COMMIT();

    int rowA = warpM * 32 + (lane & 15);
    int colA = (lane >> 4) << 3;
    int rowB = warpN * 64 + (lane & 7) + ((lane >> 4) << 3);
    int colB = ((lane >> 3) & 1) << 3;
    uint32_t offA = (uint32_t)(rowA * LDPH + colA) * 2;
    uint32_t offB = (uint32_t)(TILE_H + rowB * LDPH + colB) * 2;

    for (int t = 0; t < T; t++) {
        int buf = t % 3;
        CP_WAIT1();
        __syncthreads();
        if (t + 2 < T) load_tile(t + 2, (t + 2) % 3);
        CP_COMMIT();

        uint32_t sA = sbase + (uint32_t)buf * STAGE_H * 2;

        #pragma unroll
        for (int kk = 0; kk < BK / 16; kk++) {
            uint32_t af[2][4];
            #pragma unroll
            for (int mt = 0; mt < 2; mt++) {
                uint32_t addr = sA + offA + (uint32_t)(mt * 16 * LDPH + kk * 16) * 2;
                ldsm4(af[mt][0], af[mt][1], af[mt][2], af[mt][3], addr);
            }
            uint32_t bf[8][2];
            #pragma unroll
            for (int ntp = 0; ntp < 4; ntp++) {
                uint32_t addr = sA + offB + (uint32_t)(ntp * 16 * LDPH + kk * 16) * 2;
                ldsm4(bf[2 * ntp][0], bf[2 * ntp][1],
                      bf[2 * ntp + 1][0], bf[2 * ntp + 1][1], addr);
            }
            #pragma unroll
            for (int mt = 0; mt < 2; mt++)
                #pragma unroll
                for (int nt = 0; nt < 8; nt++)
                    mma16(acc[mt][nt], af[mt], bf[nt]);
        }
    }

    #pragma unroll
    for (int mt = 0; mt < 2; mt++) {
        #pragma unroll
        for (int half_ = 0; half_ < 2; half_++) {
            int row = m0 + warpM * 32 + mt * 16 + (lane >> 2) + half_ * 8;
            if (row >= Mrows) continue;
            int bI = (row >= Nn) ? 1 : 0;
            #pragma unroll
            for (int nt = 0; nt < 8; nt++) {
                int col = n0 + warpN * 64 + nt * 8 + (lane & 3) * 2;
                if (col >= Nstore) continue;
                float v0 = acc[mt][nt][half_ * 2];
                float v1 = acc[mt][nt][half_ * 2 + 1];
                if (BIAS) { v0 += bias[col]; v1 += bias[col + 1]; }
                if (EPI == 1) { v0 = fsilu(v0); v1 = fsilu(v1); }
                if (EPI == 2) {
                    v0 += res[(size_t)row * ldo + col];
                    v1 += res[(size_t)row * ldo + col + 1];
                }
                if (EPI == 3) {
                    v0 = res[(size_t)row * ldo + col]     + gate[bI * gateStride + col]     * v0;
                    v1 = res[(size_t)row * ldo + col + 1] + gate[bI * gateStride + col + 1] * v1;
                }
                if (WF) *(float2*)&Of[(size_t)row * ldo + col] = make_float2(v0, v1);
                if (WH) *(__half2*)&Oh[(size_t)row * ldo + col] = __floats2half2_rn(v0, v1);
                if (VT) {
                    if (col >= Cc) {
                        int bb = row / Mkv, m = row - bb * Mkv;
                        int hd = col - Cc;
                        int hh = hd / 72, dd = hd - hh * 72;
                        __half* vb = vtout + ((size_t)(bb * HX + hh) * 72 + dd) * SLD + m;
                        vb[0]   = __float2half_rn(v0);
                        vb[SLD] = __float2half_rn(v1);
                    }
                }
            }
        }
    }
}

// ---------------------------------------------------------------------------
// prologue: weight/y fp16 conversion + m=sst+t + vk zero + vt zero, ONE launch
// ---------------------------------------------------------------------------
__global__ void round_all_kernel(const float* qkv_w, const float* aproj_w,
                                 const float* q_w, const float* kv_w,
                                 const float* cproj_w, const float* inv_w,
                                 const float* pw_w, const float* y,
                                 const float* t, const float* sst)
{
    long i = (long)blockIdx.x * 256 + threadIdx.x;
    long n;
    n = (long)3 * Cc * Cc;   if (i < n) { g_wts[W_QKV + i] = __float2half_rn(qkv_w[i]);   return; } i -= n;
    n = (long)Cc * Cc;       if (i < n) { g_wts[W_APR + i] = __float2half_rn(aproj_w[i]); return; } i -= n;
    n = (long)Cc * Cc;       if (i < n) { g_wts[W_Q   + i] = __float2half_rn(q_w[i]);     return; } i -= n;
    n = (long)2 * Cc * Cc;   if (i < n) { g_wts[W_KV  + i] = __float2half_rn(kv_w[i]);    return; } i -= n;
    n = (long)Cc * Cc;       if (i < n) { g_wts[W_CPR + i] = __float2half_rn(cproj_w[i]); return; } i -= n;
    n = (long)2 * HIDd * Cc; if (i < n) { g_wts[W_INV + i] = __float2half_rn(inv_w[i]);   return; } i -= n;
    n = (long)Cc * HIDd;     if (i < n) { g_wts[W_PW  + i] = __float2half_rn(pw_w[i]);    return; } i -= n;
    n = (long)Bb * Mkv * Cc; if (i < n) { g_yh[i] = __float2half_rn(y[i]);                return; } i -= n;
    n = (long)Bb * 6 * Cc;   if (i < n) { g_mb[i] = sst[i % (6 * Cc)] + t[i];             return; } i -= n;
    n = (long)Bb * HLA * 33 * 32; if (i < n) { g_vk[i] = 0.f;                             return; } i -= n;
    n = (long)Bb * HX * 72 * SLD; if (i < n) { g_vt[i] = __float2half_rn(0.f); }
}

// ---------------------------------------------------------------------------
__global__ __launch_bounds__(256)
void ln_mod_kernel(const float* __restrict__ in, __half* __restrict__ out,
                   int scRow, int shRow)
{
    int row = blockIdx.x;
    int b   = row / Nn;
    const float* xr = in + (size_t)row * Cc;

    float s = 0.f, s2 = 0.f;
    for (int c = threadIdx.x; c < Cc; c += blockDim.x) {
        float v = xr[c]; s += v; s2 += v * v;
    }
    __shared__ float sh1[8], sh2[8];
    int lane = threadIdx.x & 31, wid = threadIdx.x >> 5;
    #pragma unroll
    for (int o = 16; o > 0; o >>= 1) {
        s  += __shfl_down_sync(0xffffffffu, s,  o);
        s2 += __shfl_down_sync(0xffffffffu, s2, o);
    }
    if (lane == 0) { sh1[wid] = s; sh2[wid] = s2; }
    __syncthreads();
    if (wid == 0) {
        s  = (lane < 8) ? sh1[lane] : 0.f;
        s2 = (lane < 8) ? sh2[lane] : 0.f;
        #pragma unroll
        for (int o = 4; o > 0; o >>= 1) {
            s  += __shfl_down_sync(0xffffffffu, s,  o);
            s2 += __shfl_down_sync(0xffffffffu, s2, o);
        }
        if (lane == 0) { sh1[0] = s; sh2[0] = s2; }
    }
    __syncthreads();
    float mu   = sh1[0] * (1.f / Cc);
    float var  = sh2[0] * (1.f / Cc) - mu * mu;
    float rstd = rsqrtf(var + 1e-6f);
    const float* mbp = g_mb + (size_t)b * 6 * Cc;
    for (int c = threadIdx.x; c < Cc; c += blockDim.x) {
        float sc = mbp[scRow * Cc + c];
        float sv = mbp[shRow * Cc + c];
        out[(size_t)row * Cc + c] =
            __float2half_rn((xr[c] - mu) * rstd * (1.f + sc) + sv);
    }
}

// ---------------------------------------------------------------------------
// LiteLA vk accumulation (transposed out): 352 threads, 3 exact units each
// ---------------------------------------------------------------------------
__global__ __launch_bounds__(352)
void vk_kernel(const __half* __restrict__ qkv, float* __restrict__ vkout)
{
    int bh = blockIdx.x;
    int b  = bh / HLA, h = bh % HLA;
    int split = blockIdx.y;
    __shared__ float ks[32][33];
    __shared__ float vs[32][33];
    float acc[3] = {0.f, 0.f, 0.f};
    int tid = threadIdx.x;
    const size_t base = (size_t)b * Nn * 3 * Cc;
    int nStart = split * (Nn / 16);
    for (int n0 = nStart; n0 < nStart + Nn / 16; n0 += 32) {
        for (int li = tid; li < 1024; li += 352) {
            int nn = li >> 5, dc = li & 31;
            size_t off = base + (size_t)(n0 + nn) * 3 * Cc + h * 32 + dc;
            ks[nn][dc] = fmaxf(__half2float(qkv[off + Cc]), 0.f);
            vs[nn][dc] = __half2float(qkv[off + 2 * Cc]);
        }
        __syncthreads();
        #pragma unroll
        for (int u = 0; u < 3; u++) {
            int idx = tid + 352 * u;             // 0..1055 exact
            int e = idx >> 5, dc = idx & 31;
            float a = acc[u];
            if (e == 32) {
                #pragma unroll
                for (int nn = 0; nn < 32; nn++) a += ks[nn][dc];
            } else {
                #pragma unroll
                for (int nn = 0; nn < 32; nn++) a += vs[nn][e] * ks[nn][dc];
            }
            acc[u] = a;
        }
        __syncthreads();
    }
    #pragma unroll
    for (int u = 0; u < 3; u++) {
        int idx = tid + 352 * u;
        int e = idx >> 5, dc = idx & 31;
        atomicAdd(&vkout[((size_t)bh * 32 + dc) * 33 + e], acc[u]);
    }
}

__global__ __launch_bounds__(256)
void la_out_kernel(const __half* __restrict__ qkv, const float* __restrict__ vk,
                   __half* __restrict__ out)
{
    int row = blockIdx.x;
    int b   = row / Nn;
    __shared__ float q[Cc];
    __shared__ float rden[HLA];
    const __half* qr = qkv + (size_t)row * 3 * Cc;
    for (int c = threadIdx.x; c < Cc; c += blockDim.x)
        q[c] = fmaxf(__half2float(qr[c]), 0.f);
    __syncthreads();
    if (threadIdx.x < HLA) {
        int h = threadIdx.x;
        const float* vkh = vk + (size_t)(b * HLA + h) * 32 * 33;
        float s = 0.f;
        #pragma unroll
        for (int d = 0; d < 32; d++) s += vkh[d * 33 + 32] * q[h * 32 + d];
        rden[h] = 1.0f / (s + 1e-8f);
    }
    __syncthreads();
    for (int c = threadIdx.x; c < Cc; c += blockDim.x) {
        int h = c >> 5, dd = c & 31;
        const float* vkr = vk + (size_t)(b * HLA + h) * 32 * 33 + dd;
        const float* qh  = q + h * 32;
        float s = 0.f;
        #pragma unroll
        for (int d = 0; d < 32; d++) s += vkr[d * 33] * qh[d];
        out[(size_t)row * Cc + c] = __float2half_rn(s * rden[h]);
    }
}

// ---------------------------------------------------------------------------
__global__ __launch_bounds__(256)
void softmax_kernel(const float* __restrict__ s, __half* __restrict__ p, long rows)
{
    long gw  = ((long)blockIdx.x * blockDim.x + threadIdx.x) >> 5;
    int lane = threadIdx.x & 31;
    if (gw >= rows) return;
    const float* r = s + gw * SLD;
    __half* rp = p + gw * SLD;
    const float scale = 0.11785113019775793f;
    float v[10];
    float mx = -1e30f;
    #pragma unroll
    for (int i = 0; i < 10; i++) {
        int m = lane + 32 * i;
        v[i] = (m < Mkv) ? r[m] * scale : -1e30f;
        mx = fmaxf(mx, v[i]);
    }
    #pragma unroll
    for (int o = 16; o > 0; o >>= 1) mx = fmaxf(mx, __shfl_xor_sync(0xffffffffu, mx, o));
    float sum = 0.f;
    #pragma unroll
    for (int i = 0; i < 10; i++) { v[i] = fexp(v[i] - mx); sum += v[i]; }
    #pragma unroll
    for (int o = 16; o > 0; o >>= 1) sum += __shfl_xor_sync(0xffffffffu, sum, o);
    float inv = 1.f / sum;
    #pragma unroll
    for (int i = 0; i < 10; i++) {
        int m = lane + 32 * i;
        rp[m] = __float2half_rn((m < Mkv) ? v[i] * inv : 0.f);
    }
}

// ---------------------------------------------------------------------------
__global__ __launch_bounds__(256)
void dwglu_kernel(const __half* __restrict__ h, const float* __restrict__ dww,
                  const float* __restrict__ dwb, __half* __restrict__ out)
{
    __shared__ float sa[100][64];
    __shared__ float sg[100][64];
    int tid = threadIdx.x;
    int c0  = blockIdx.x * 64;
    int y0  = (blockIdx.y >> 3) * 8, x0 = (blockIdx.y & 7) * 8;
    int b   = blockIdx.z;

    int ch = tid & 63;
    float wA[9], wG[9];
    #pragma unroll
    for (int tp = 0; tp < 9; tp++) {
        wA[tp] = dww[(size_t)(c0 + ch) * 9 + tp];
        wG[tp] = dww[(size_t)(c0 + ch + HIDd) * 9 + tp];
    }
    float bA = dwb[c0 + ch], bG = dwb[c0 + ch + HIDd];

    for (int li = tid; li < 1600; li += 256) {
        int pos = li >> 4, q = li & 15;
        int py = pos / 10, px = pos % 10;
        int yy = y0 + py - 1, xx = x0 + px - 1;
        float4 va = make_float4(0.f, 0.f, 0.f, 0.f), vg = va;
        if (yy >= 0 && yy < 64 && xx >= 0 && xx < 64) {
            const __half* src = h + ((size_t)b * Nn + yy * 64 + xx) * (2 * HIDd) + c0 + q * 4;
            float2 a01 = __half22float2(*(const __half2*)src);
            float2 a23 = __half22float2(*(const __half2*)(src + 2));
            float2 g01 = __half22float2(*(const __half2*)(src + HIDd));
            float2 g23 = __half22float2(*(const __half2*)(src + HIDd + 2));
            va = make_float4(a01.x, a01.y, a23.x, a23.y);
            vg = make_float4(g01.x, g01.y, g23.x, g23.y);
        }
        *(float4*)&sa[pos][q * 4] = va;
        *(float4*)&sg[pos][q * 4] = vg;
    }
    __syncthreads();

    #pragma unroll
    for (int i = 0; i < 16; i++) {
        int pos = (tid >> 6) + i * 4;
        int py = pos >> 3, px = pos & 7;
        int s0 = (py + 1) * 10 + (px + 1);
        float accA = bA, accG = bG;
        #pragma unroll
        for (int dy = -1; dy <= 1; dy++)
            #pragma unroll
            for (int dx = -1; dx <= 1; dx++) {
                int s = s0 + dy * 10 + dx;
                int tp = (dy + 1) * 3 + (dx + 1);
                accA = fmaf(sa[s][ch], wA[tp], accA);
                accG = fmaf(sg[s][ch], wG[tp], accG);
            }
        int n = (y0 + py) * 64 + (x0 + px);
        out[((size_t)b * Nn + n) * HIDd + c0 + ch] =
            __float2half_rn(accA * fsilu(accG));
    }
}

// ---------------------------------------------------------------------------
extern "C" void kernel_launch(void* const* d_in, const int* /*in_sizes*/, int /*n_in*/,
                              void* d_out, int /*out_size*/)
{
    const float* x       = (const float*)d_in[0];
    const float* y       = (const float*)d_in[1];
    const float* t       = (const float*)d_in[2];
    const float* sst     = (const float*)d_in[3];
    const float* qkv_w   = (const float*)d_in[4];
    const float* aproj_w = (const float*)d_in[5];
    const float* aproj_b = (const float*)d_in[6];
    const float* q_w     = (const float*)d_in[7];
    const float* q_b     = (const float*)d_in[8];
    const float* kv_w    = (const float*)d_in[9];
    const float* kv_b    = (const float*)d_in[10];
    const float* cproj_w = (const float*)d_in[11];
    const float* cproj_b = (const float*)d_in[12];
    const float* inv_w   = (const float*)d_in[13];
    const float* inv_b   = (const float*)d_in[14];
    const float* dw_w    = (const float*)d_in[15];
    const float* dw_b    = (const float*)d_in[16];
    const float* pw_w    = (const float*)d_in[17];
    float* out = (float*)d_out;

    float  *p_big, *p_x1, *p_x2, *p_vk, *p_m;
    __half *p_shh, *p_x1h, *p_glu, *p_kvh, *p_vt, *p_prb, *p_yh, *p_w;
    cudaGetSymbolAddress((void**)&p_big, g_big);
    cudaGetSymbolAddress((void**)&p_shh, g_shh);
    cudaGetSymbolAddress((void**)&p_x1,  g_x1);
    cudaGetSymbolAddress((void**)&p_x1h, g_x1h);
    cudaGetSymbolAddress((void**)&p_x2,  g_x2);
    cudaGetSymbolAddress((void**)&p_glu, g_glu);
    cudaGetSymbolAddress((void**)&p_kvh, g_kvb);
    cudaGetSymbolAddress((void**)&p_vt,  g_vt);
    cudaGetSymbolAddress((void**)&p_prb, g_prb);
    cudaGetSymbolAddress((void**)&p_yh,  g_yh);
    cudaGetSymbolAddress((void**)&p_vk,  g_vk);
    cudaGetSymbolAddress((void**)&p_m,   g_mb);
    cudaGetSymbolAddress((void**)&p_w,   g_wts);

    __half* p_bigh = (__half*)p_big;

    cudaFuncSetAttribute(mma_gemm<false,0,false,true ,64,false>, cudaFuncAttributeMaxDynamicSharedMemorySize, MM_SMEM64);
    cudaFuncSetAttribute(mma_gemm<true ,3,true ,true ,64,false>, cudaFuncAttributeMaxDynamicSharedMemorySize, MM_SMEM64);
    cudaFuncSetAttribute(mma_gemm<true ,0,false,true ,64,false>, cudaFuncAttributeMaxDynamicSharedMemorySize, MM_SMEM64);
    cudaFuncSetAttribute(mma_gemm<true ,0,false,true ,64,true >, cudaFuncAttributeMaxDynamicSharedMemorySize, MM_SMEM64);
    cudaFuncSetAttribute(mma_gemm<false,0,true ,false,32,false>, cudaFuncAttributeMaxDynamicSharedMemorySize, MM_SMEM32);
    cudaFuncSetAttribute(mma_gemm<true ,2,true ,false,64,false>, cudaFuncAttributeMaxDynamicSharedMemorySize, MM_SMEM64);
    cudaFuncSetAttribute(mma_gemm<true ,1,false,true ,64,false>, cudaFuncAttributeMaxDynamicSharedMemorySize, MM_SMEM64);
    cudaFuncSetAttribute(mma_gemm<false,3,true ,false,64,false>, cudaFuncAttributeMaxDynamicSharedMemorySize, MM_SMEM64);

    const int ROWS = Bb * Nn;
    const long RN_TOTAL = (long)3*Cc*Cc + 5L*Cc*Cc + 2L*HIDd*Cc + (long)Cc*HIDd
                        + (long)Bb*Mkv*Cc + (long)Bb*6*Cc
                        + (long)Bb*HLA*33*32 + (long)Bb*HX*72*SLD;

    round_all_kernel<<<(int)((RN_TOTAL + 255) / 256), 256>>>(
        qkv_w, aproj_w, q_w, kv_w, cproj_w, inv_w, pw_w, y, t, sst);
    ln_mod_kernel<<<ROWS, 256>>>(x, p_shh, 1, 0);

    // qkv = xmod1 @ qkv_w.T
    mma_gemm<false,0,false,true,64,false><<<dim3(27, 64), 256, MM_SMEM64>>>(
        p_shh, p_w + W_QKV, nullptr, nullptr, nullptr, nullptr, p_bigh, nullptr,
        ROWS, 3 * Cc, 3 * Cc, Cc, Cc, Cc, 3 * Cc,
        1, 0, 0, 0, 0, 0, 0, 0);

    vk_kernel<<<dim3(Bb * HLA, 16), 352>>>(p_bigh, p_vk);
    la_out_kernel<<<ROWS, 256>>>(p_bigh, p_vk, p_shh);

    // x1 = x + g_a * (la @ aproj_w.T + b)
    mma_gemm<true,3,true,true,64,false><<<dim3(9, 64), 256, MM_SMEM64>>>(
        p_shh, p_w + W_APR, aproj_b, x, p_m + 2 * Cc, p_x1, p_x1h, nullptr,
        ROWS, Cc, Cc, Cc, Cc, Cc, Cc,
        1, 0, 0, 0, 0, 0, 0, 6 * Cc);

    // q = x1 @ q_w.T + q_b
    mma_gemm<true,0,false,true,64,false><<<dim3(9, 64), 256, MM_SMEM64>>>(
        p_x1h, p_w + W_Q, q_b, nullptr, nullptr, nullptr, p_shh, nullptr,
        ROWS, Cc, Cc, Cc, Cc, Cc, Cc,
        1, 0, 0, 0, 0, 0, 0, 0);

    // kv = y @ kv_w.T + kv_b  (+ fused v^T scatter)
    mma_gemm<true,0,false,true,64,true><<<dim3(18, 5), 256, MM_SMEM64>>>(
        p_yh, p_w + W_KV, kv_b, nullptr, nullptr, nullptr, p_kvh, p_vt,
        Bb * Mkv, 2 * Cc, 2 * Cc, Cc, Cc, Cc, 2 * Cc,
        1, 0, 0, 0, 0, 0, 0, 0);

    // scores[z] = q_h @ k_h.T  (BK=32; store only the 300 real cols)
    mma_gemm<false,0,true,false,32,false><<<dim3(3, 32, Bb * HX), 256, MM_SMEM32>>>(
        p_shh, p_kvh, nullptr, nullptr, nullptr, p_big, nullptr, nullptr,
        Nn, Mkv, Mkv, 72, Cc, 2 * Cc, SLD,
        HX, (long)Nn * Cc, 72, (long)Mkv * 2 * Cc, 72,
        (long)HX * Nn * SLD, (long)Nn * SLD, 0);

    softmax_kernel<<<(Bb * HX * Nn) / 8, 256>>>(p_big, p_prb, (long)Bb * HX * Nn);

    // o[z] = probs @ v^T
    mma_gemm<false,0,false,true,64,false><<<dim3(1, 32, Bb * HX), 256, MM_SMEM64>>>(
        p_prb, p_vt, nullptr, nullptr, nullptr, nullptr, p_shh, nullptr,
        Nn, 72, 72, SLD, SLD, SLD, Cc,
        HX, (long)HX * Nn * SLD, (long)Nn * SLD, (long)72 * SLD * HX, (long)72 * SLD,
        (long)Nn * Cc, 72, 0);

    // x2 = x1 + o @ cproj_w.T + b
    mma_gemm<true,2,true,false,64,false><<<dim3(9, 64), 256, MM_SMEM64>>>(
        p_shh, p_w + W_CPR, cproj_b, p_x1, nullptr, p_x2, nullptr, nullptr,
        ROWS, Cc, Cc, Cc, Cc, Cc, Cc,
        1, 0, 0, 0, 0, 0, 0, 0);

    ln_mod_kernel<<<ROWS, 256>>>(p_x2, p_shh, 4, 3);

    // h = silu(xmod2 @ inv_w.T + b)
    mma_gemm<true,1,false,true,64,false><<<dim3(45, 64), 256, MM_SMEM64>>>(
        p_shh, p_w + W_INV, inv_b, nullptr, nullptr, nullptr, p_bigh, nullptr,
        ROWS, 2 * HIDd, 2 * HIDd, Cc, Cc, Cc, 2 * HIDd,
        1, 0, 0, 0, 0, 0, 0, 0);

    dwglu_kernel<<<dim3(HIDd / 64, 64, Bb), 256>>>(p_bigh, dw_w, dw_b, p_glu);

    // out = x2 + g_m * (glu @ pw_w.T)
    mma_gemm<false,3,true,false,64,false><<<dim3(9, 64), 256, MM_SMEM64>>>(
        p_glu, p_w + W_PW, nullptr, p_x2, p_m + 5 * Cc, out, nullptr, nullptr,
        ROWS, Cc, Cc, HIDd, HIDd, HIDd, Cc,
        1, 0, 0, 0, 0, 0, 0, 6 * Cc);
}

// round 16
// speedup vs baseline: 1.0016x; 1.0016x over previous
#include <cuda_runtime.h>
#include <cuda_fp16.h>
#include <cstdint>
#include <math.h>

// ---------------------------------------------------------------------------
// SanaBlock: LN+adaLN -> LiteLA -> cross-attn -> GLUMBConv, B=2,N=4096,C=1152
// R16: la_out 4 rows/CTA (vk L2 traffic /4), vk split-K 32 (more gather MLP).
//      Everything else as R15.
// ---------------------------------------------------------------------------
constexpr int Bb   = 2;
constexpr int Nn   = 4096;
constexpr int Cc   = 1152;
constexpr int Mkv  = 300;
constexpr int HIDd = 2880;
constexpr int HLA  = 36;
constexpr int HX   = 16;
constexpr int SLD  = 320;

__device__ __align__(256) float  g_big [47185920];
__device__ __align__(256) __half g_shh [(size_t)Bb * Nn * Cc];
__device__ __align__(256) float  g_x1  [(size_t)Bb * Nn * Cc];
__device__ __align__(256) __half g_x1h [(size_t)Bb * Nn * Cc];
__device__ __align__(256) float  g_x2  [(size_t)Bb * Nn * Cc];
__device__ __align__(256) __half g_glu [(size_t)Bb * Nn * HIDd];
__device__ __align__(256) __half g_kvb [(size_t)Bb * Mkv * 2 * Cc];
__device__ __align__(256) __half g_vt  [(size_t)Bb * HX * 72 * SLD];
__device__ __align__(256) __half g_prb [(size_t)Bb * HX * Nn * SLD];
__device__ __align__(256) __half g_yh  [(size_t)Bb * Mkv * Cc];
__device__ __align__(256) __half g_wts [20570112];
__device__ float g_vk [Bb * HLA * 33 * 32];   // transposed: [bh][d:32][e:33]
__device__ float g_mb [Bb * 6 * Cc];

constexpr size_t W_QKV = 0;
constexpr size_t W_APR = W_QKV + (size_t)3 * Cc * Cc;
constexpr size_t W_Q   = W_APR + (size_t)Cc * Cc;
constexpr size_t W_KV  = W_Q   + (size_t)Cc * Cc;
constexpr size_t W_CPR = W_KV  + (size_t)2 * Cc * Cc;
constexpr size_t W_INV = W_CPR + (size_t)Cc * Cc;
constexpr size_t W_PW  = W_INV + (size_t)2 * HIDd * Cc;

// ---------------------------------------------------------------------------
// FMA-only transcendentals
// ---------------------------------------------------------------------------
__device__ __forceinline__ float fexp(float t){
    t = fminf(fmaxf(t, -87.0f), 87.0f);
    float z = t * 1.4426950408889634f;
    float n = floorf(z);
    float f = z - n;
    float p = 1.5403530e-4f;
    p = fmaf(p, f, 1.3333558e-3f);
    p = fmaf(p, f, 9.6181291e-3f);
    p = fmaf(p, f, 5.5504109e-2f);
    p = fmaf(p, f, 2.4022651e-1f);
    p = fmaf(p, f, 6.9314718e-1f);
    p = fmaf(p, f, 1.0f);
    int i = (int)n;
    return p * __int_as_float((i + 127) << 23);
}
__device__ __forceinline__ float fsigmoid(float x){
    float u = fexp(-fabsf(x));
    float z = 1.0f + u;                    // [1,2]
    float y = fmaf(-0.47058824f, z, 1.4117647f);
    y = y * fmaf(-z, y, 2.0f);
    y = y * fmaf(-z, y, 2.0f);
    return (x >= 0.f) ? y : 1.0f - y;
}
__device__ __forceinline__ float fsilu(float x){ return x * fsigmoid(x); }

// ---------------------------------------------------------------------------
// helpers
// ---------------------------------------------------------------------------
__device__ __forceinline__ uint32_t smem_u32(const void* p){
    uint32_t a;
    asm("{ .reg .u64 t; cvta.to.shared.u64 t, %1; cvt.u32.u64 %0, t; }"
        : "=r"(a) : "l"(p));
    return a;
}
__device__ __forceinline__ void cp16(uint32_t dst, const void* src, int srcsz){
    asm volatile("cp.async.cg.shared.global [%0], [%1], 16, %2;"
        ::"r"(dst),"l"(src),"r"(srcsz):"memory");
}
#define CP_COMMIT() asm volatile("cp.async.commit_group;":::"memory")
#define CP_WAIT1()  asm volatile("cp.async.wait_group 1;":::"memory")

__device__ __forceinline__ void mma16(float* d, const uint32_t* a, const uint32_t* b){
    asm volatile("mma.sync.aligned.m16n8k16.row.col.f32.f16.f16.f32 "
        "{%0,%1,%2,%3},{%4,%5,%6,%7},{%8,%9},{%0,%1,%2,%3};"
        : "+f"(d[0]),"+f"(d[1]),"+f"(d[2]),"+f"(d[3])
        : "r"(a[0]),"r"(a[1]),"r"(a[2]),"r"(a[3]),"r"(b[0]),"r"(b[1]));
}
__device__ __forceinline__ void ldsm4(uint32_t& r0, uint32_t& r1, uint32_t& r2,
                                      uint32_t& r3, uint32_t addr){
    asm volatile("ldmatrix.sync.aligned.m8n8.x4.shared.b16 {%0,%1,%2,%3}, [%4];"
        : "=r"(r0),"=r"(r1),"=r"(r2),"=r"(r3) : "r"(addr));
}

// ---------------------------------------------------------------------------
// fp16 mma NT GEMM, BK templated (32 or 64): 3-stage cp.async, 1 barrier/tile.
// CTA 128x128, 8 warps (4M x 2N), warp tile 32x64, ldmatrix.x4 fragments.
// VT: scatter v-half of kv output into g_vt (transposed, padded).
// ---------------------------------------------------------------------------
template<int BK> struct GK {
    static constexpr int LDPH    = BK + 8;
    static constexpr int TILE_H  = 128 * LDPH;
    static constexpr int STAGE_H = 2 * TILE_H;
    static constexpr int SMEM    = 3 * STAGE_H * 2;
};
constexpr int MM_SMEM64 = GK<64>::SMEM;   // 110592
constexpr int MM_SMEM32 = GK<32>::SMEM;   // 61440

template<bool BIAS, int EPI, bool WF, bool WH, int BK, bool VT>
__global__ __launch_bounds__(256, 2)
void mma_gemm(const __half* A, const __half* Bw, const float* bias,
              const float* res, const float* gate,
              float* Of, __half* Oh, __half* vtout,
              int Mrows, int NloadB, int Nstore, int K,
              int lda, int ldb, int ldo,
              int HB, long aBs, long aHs, long bBs, long bHs, long oBs, long oHs,
              int gateStride)
{
    constexpr int LDPH    = GK<BK>::LDPH;
    constexpr int TILE_H  = GK<BK>::TILE_H;
    constexpr int STAGE_H = GK<BK>::STAGE_H;
    constexpr int CPR     = BK / 8;
    constexpr int LITER   = BK / 16;

    extern __shared__ __half smh[];
    uint32_t sbase = smem_u32(smh);
    int tid = threadIdx.x, wid = tid >> 5, lane = tid & 31;
    int warpM = wid >> 1, warpN = wid & 1;
    int m0 = blockIdx.y * 128, n0 = blockIdx.x * 128;

    if (gridDim.z > 1) {
        int z = blockIdx.z;
        int bI = z / HB, hI = z % HB;
        A  += bI * aBs + hI * aHs;
        Bw += bI * bBs + hI * bHs;
        if (WF) Of += bI * oBs + hI * oHs;
        if (WH) Oh += bI * oBs + hI * oHs;
    }

    const int T = (K + BK - 1) / BK;

    auto load_tile = [&](int t, int buf) {
        uint32_t base = sbase + (uint32_t)buf * STAGE_H * 2;
        int k0 = t * BK;
        #pragma unroll
        for (int i = 0; i < LITER; i++) {
            int c = tid + (i << 8);
            int row = c / CPR, ch = c % CPR;
            int gk = k0 + ch * 8;
            uint32_t dst = base + (uint32_t)(row * LDPH + ch * 8) * 2;
            const __half* ga = A + (size_t)(m0 + row) * lda + gk;
            cp16(dst, ga, ((m0 + row) < Mrows && gk < K) ? 16 : 0);
        }
        #pragma unroll
        for (int i = 0; i < LITER; i++) {
            int c = tid + (i << 8);
            int row = c / CPR, ch = c % CPR;
            int gk = k0 + ch * 8;
            uint32_t dst = base + (uint32_t)(TILE_H + row * LDPH + ch * 8) * 2;
            const __half* gb = Bw + (size_t)(n0 + row) * ldb + gk;
            cp16(dst, gb, ((n0 + row) < NloadB && gk < K) ? 16 : 0);
        }
    };

    float acc[2][8][4];
    #pragma unroll
    for (int mt = 0; mt < 2; mt++)
        #pragma unroll
        for (int nt = 0; nt < 8; nt++)
            #pragma unroll
            for (int q = 0; q < 4; q++) acc[mt][nt][q] = 0.f;

    load_tile(0, 0); CP_COMMIT();
    load_tile(1, 1); CP_COMMIT();

    int rowA = warpM * 32 + (lane & 15);
    int colA = (lane >> 4) << 3;
    int rowB = warpN * 64 + (lane & 7) + ((lane >> 4) << 3);
    int colB = ((lane >> 3) & 1) << 3;
    uint32_t offA = (uint32_t)(rowA * LDPH + colA) * 2;
    uint32_t offB = (uint32_t)(TILE_H + rowB * LDPH + colB) * 2;

    for (int t = 0; t < T; t++) {
        int buf = t % 3;
        CP_WAIT1();
        __syncthreads();
        if (t + 2 < T) load_tile(t + 2, (t + 2) % 3);
        CP_COMMIT();

        uint32_t sA = sbase + (uint32_t)buf * STAGE_H * 2;

        #pragma unroll
        for (int kk = 0; kk < BK / 16; kk++) {
            uint32_t af[2][4];
            #pragma unroll
            for (int mt = 0; mt < 2; mt++) {
                uint32_t addr = sA + offA + (uint32_t)(mt * 16 * LDPH + kk * 16) * 2;
                ldsm4(af[mt][0], af[mt][1], af[mt][2], af[mt][3], addr);
            }
            uint32_t bf[8][2];
            #pragma unroll
            for (int ntp = 0; ntp < 4; ntp++) {
                uint32_t addr = sA + offB + (uint32_t)(ntp * 16 * LDPH + kk * 16) * 2;
                ldsm4(bf[2 * ntp][0], bf[2 * ntp][1],
                      bf[2 * ntp + 1][0], bf[2 * ntp + 1][1], addr);
            }
            #pragma unroll
            for (int mt = 0; mt < 2; mt++)
                #pragma unroll
                for (int nt = 0; nt < 8; nt++)
                    mma16(acc[mt][nt], af[mt], bf[nt]);
        }
    }

    #pragma unroll
    for (int mt = 0; mt < 2; mt++) {
        #pragma unroll
        for (int half_ = 0; half_ < 2; half_++) {
            int row = m0 + warpM * 32 + mt * 16 + (lane >> 2) + half_ * 8;
            if (row >= Mrows) continue;
            int bI = (row >= Nn) ? 1 : 0;
            #pragma unroll
            for (int nt = 0; nt < 8; nt++) {
                int col = n0 + warpN * 64 + nt * 8 + (lane & 3) * 2;
                if (col >= Nstore) continue;
                float v0 = acc[mt][nt][half_ * 2];
                float v1 = acc[mt][nt][half_ * 2 + 1];
                if (BIAS) { v0 += bias[col]; v1 += bias[col + 1]; }
                if (EPI == 1) { v0 = fsilu(v0); v1 = fsilu(v1); }
                if (EPI == 2) {
                    v0 += res[(size_t)row * ldo + col];
                    v1 += res[(size_t)row * ldo + col + 1];
                }
                if (EPI == 3) {
                    v0 = res[(size_t)row * ldo + col]     + gate[bI * gateStride + col]     * v0;
                    v1 = res[(size_t)row * ldo + col + 1] + gate[bI * gateStride + col + 1] * v1;
                }
                if (WF) *(float2*)&Of[(size_t)row * ldo + col] = make_float2(v0, v1);
                if (WH) *(__half2*)&Oh[(size_t)row * ldo + col] = __floats2half2_rn(v0, v1);
                if (VT) {
                    if (col >= Cc) {
                        int bb = row / Mkv, m = row - bb * Mkv;
                        int hd = col - Cc;
                        int hh = hd / 72, dd = hd - hh * 72;
                        __half* vb = vtout + ((size_t)(bb * HX + hh) * 72 + dd) * SLD + m;
                        vb[0]   = __float2half_rn(v0);
                        vb[SLD] = __float2half_rn(v1);
                    }
                }
            }
        }
    }
}

// ---------------------------------------------------------------------------
// prologue: weight/y fp16 conversion + m=sst+t + vk zero + vt zero, ONE launch
// ---------------------------------------------------------------------------
__global__ void round_all_kernel(const float* qkv_w, const float* aproj_w,
                                 const float* q_w, const float* kv_w,
                                 const float* cproj_w, const float* inv_w,
                                 const float* pw_w, const float* y,
                                 const float* t, const float* sst)
{
    long i = (long)blockIdx.x * 256 + threadIdx.x;
    long n;
    n = (long)3 * Cc * Cc;   if (i < n) { g_wts[W_QKV + i] = __float2half_rn(qkv_w[i]);   return; } i -= n;
    n = (long)Cc * Cc;       if (i < n) { g_wts[W_APR + i] = __float2half_rn(aproj_w[i]); return; } i -= n;
    n = (long)Cc * Cc;       if (i < n) { g_wts[W_Q   + i] = __float2half_rn(q_w[i]);     return; } i -= n;
    n = (long)2 * Cc * Cc;   if (i < n) { g_wts[W_KV  + i] = __float2half_rn(kv_w[i]);    return; } i -= n;
    n = (long)Cc * Cc;       if (i < n) { g_wts[W_CPR + i] = __float2half_rn(cproj_w[i]); return; } i -= n;
    n = (long)2 * HIDd * Cc; if (i < n) { g_wts[W_INV + i] = __float2half_rn(inv_w[i]);   return; } i -= n;
    n = (long)Cc * HIDd;     if (i < n) { g_wts[W_PW  + i] = __float2half_rn(pw_w[i]);    return; } i -= n;
    n = (long)Bb * Mkv * Cc; if (i < n) { g_yh[i] = __float2half_rn(y[i]);                return; } i -= n;
    n = (long)Bb * 6 * Cc;   if (i < n) { g_mb[i] = sst[i % (6 * Cc)] + t[i];             return; } i -= n;
    n = (long)Bb * HLA * 33 * 32; if (i < n) { g_vk[i] = 0.f;                             return; } i -= n;
    n = (long)Bb * HX * 72 * SLD; if (i < n) { g_vt[i] = __float2half_rn(0.f); }
}

// ---------------------------------------------------------------------------
__global__ __launch_bounds__(256)
void ln_mod_kernel(const float* __restrict__ in, __half* __restrict__ out,
                   int scRow, int shRow)
{
    int row = blockIdx.x;
    int b   = row / Nn;
    const float* xr = in + (size_t)row * Cc;

    float s = 0.f, s2 = 0.f;
    for (int c = threadIdx.x; c < Cc; c += blockDim.x) {
        float v = xr[c]; s += v; s2 += v * v;
    }
    __shared__ float sh1[8], sh2[8];
    int lane = threadIdx.x & 31, wid = threadIdx.x >> 5;
    #pragma unroll
    for (int o = 16; o > 0; o >>= 1) {
        s  += __shfl_down_sync(0xffffffffu, s,  o);
        s2 += __shfl_down_sync(0xffffffffu, s2, o);
    }
    if (lane == 0) { sh1[wid] = s; sh2[wid] = s2; }
    __syncthreads();
    if (wid == 0) {
        s  = (lane < 8) ? sh1[lane] : 0.f;
        s2 = (lane < 8) ? sh2[lane] : 0.f;
        #pragma unroll
        for (int o = 4; o > 0; o >>= 1) {
            s  += __shfl_down_sync(0xffffffffu, s,  o);
            s2 += __shfl_down_sync(0xffffffffu, s2, o);
        }
        if (lane == 0) { sh1[0] = s; sh2[0] = s2; }
    }
    __syncthreads();
    float mu   = sh1[0] * (1.f / Cc);
    float var  = sh2[0] * (1.f / Cc) - mu * mu;
    float rstd = rsqrtf(var + 1e-6f);
    const float* mbp = g_mb + (size_t)b * 6 * Cc;
    for (int c = threadIdx.x; c < Cc; c += blockDim.x) {
        float sc = mbp[scRow * Cc + c];
        float sv = mbp[shRow * Cc + c];
        out[(size_t)row * Cc + c] =
            __float2half_rn((xr[c] - mu) * rstd * (1.f + sc) + sv);
    }
}

// ---------------------------------------------------------------------------
// LiteLA vk accumulation (transposed out): 352 threads, split-K 32
// ---------------------------------------------------------------------------
__global__ __launch_bounds__(352)
void vk_kernel(const __half* __restrict__ qkv, float* __restrict__ vkout)
{
    int bh = blockIdx.x;
    int b  = bh / HLA, h = bh % HLA;
    int split = blockIdx.y;
    __shared__ float ks[32][33];
    __shared__ float vs[32][33];
    float acc[3] = {0.f, 0.f, 0.f};
    int tid = threadIdx.x;
    const size_t base = (size_t)b * Nn * 3 * Cc;
    int nStart = split * (Nn / 32);
    for (int n0 = nStart; n0 < nStart + Nn / 32; n0 += 32) {
        for (int li = tid; li < 1024; li += 352) {
            int nn = li >> 5, dc = li & 31;
            size_t off = base + (size_t)(n0 + nn) * 3 * Cc + h * 32 + dc;
            ks[nn][dc] = fmaxf(__half2float(qkv[off + Cc]), 0.f);
            vs[nn][dc] = __half2float(qkv[off + 2 * Cc]);
        }
        __syncthreads();
        #pragma unroll
        for (int u = 0; u < 3; u++) {
            int idx = tid + 352 * u;             // 0..1055 exact
            int e = idx >> 5, dc = idx & 31;
            float a = acc[u];
            if (e == 32) {
                #pragma unroll
                for (int nn = 0; nn < 32; nn++) a += ks[nn][dc];
            } else {
                #pragma unroll
                for (int nn = 0; nn < 32; nn++) a += vs[nn][e] * ks[nn][dc];
            }
            acc[u] = a;
        }
        __syncthreads();
    }
    #pragma unroll
    for (int u = 0; u < 3; u++) {
        int idx = tid + 352 * u;
        int e = idx >> 5, dc = idx & 31;
        atomicAdd(&vkout[((size_t)bh * 32 + dc) * 33 + e], acc[u]);
    }
}

// ---------------------------------------------------------------------------
// la_out: 4 rows per CTA; vk column loaded once into regs, reused across rows
// ---------------------------------------------------------------------------
__global__ __launch_bounds__(256)
void la_out_kernel(const __half* __restrict__ qkv, const float* __restrict__ vk,
                   __half* __restrict__ out)
{
    int row0 = blockIdx.x * 4;
    int b    = row0 / Nn;                  // Nn % 4 == 0: no straddle
    __shared__ float q[4][Cc];
    __shared__ float rden[4][HLA];

    for (int i = threadIdx.x; i < 4 * Cc; i += 256) {
        int r = i / Cc, c = i - r * Cc;
        q[r][c] = fmaxf(__half2float(qkv[(size_t)(row0 + r) * 3 * Cc + c]), 0.f);
    }
    __syncthreads();

    if (threadIdx.x < 4 * HLA) {
        int r = threadIdx.x / HLA, h = threadIdx.x - r * HLA;
        const float* vkh = vk + (size_t)(b * HLA + h) * 32 * 33;
        float s = 0.f;
        #pragma unroll
        for (int d = 0; d < 32; d++) s += vkh[d * 33 + 32] * q[r][h * 32 + d];
        rden[r][h] = 1.0f / (s + 1e-8f);
    }
    __syncthreads();

    for (int c = threadIdx.x; c < Cc; c += 256) {
        int h = c >> 5, dd = c & 31;
        const float* vkr = vk + (size_t)(b * HLA + h) * 32 * 33 + dd;
        float vreg[32];
        #pragma unroll
        for (int d = 0; d < 32; d++) vreg[d] = vkr[d * 33];
        #pragma unroll
        for (int r = 0; r < 4; r++) {
            const float* qh = &q[r][h * 32];
            float s = 0.f;
            #pragma unroll
            for (int d = 0; d < 32; d++) s += vreg[d] * qh[d];
            out[(size_t)(row0 + r) * Cc + c] = __float2half_rn(s * rden[r][h]);
        }
    }
}

// ---------------------------------------------------------------------------
__global__ __launch_bounds__(256)
void softmax_kernel(const float* __restrict__ s, __half* __restrict__ p, long rows)
{
    long gw  = ((long)blockIdx.x * blockDim.x + threadIdx.x) >> 5;
    int lane = threadIdx.x & 31;
    if (gw >= rows) return;
    const float* r = s + gw * SLD;
    __half* rp = p + gw * SLD;
    const float scale = 0.11785113019775793f;
    float v[10];
    float mx = -1e30f;
    #pragma unroll
    for (int i = 0; i < 10; i++) {
        int m = lane + 32 * i;
        v[i] = (m < Mkv) ? r[m] * scale : -1e30f;
        mx = fmaxf(mx, v[i]);
    }
    #pragma unroll
    for (int o = 16; o > 0; o >>= 1) mx = fmaxf(mx, __shfl_xor_sync(0xffffffffu, mx, o));
    float sum = 0.f;
    #pragma unroll
    for (int i = 0; i < 10; i++) { v[i] = fexp(v[i] - mx); sum += v[i]; }
    #pragma unroll
    for (int o = 16; o > 0; o >>= 1) sum += __shfl_xor_sync(0xffffffffu, sum, o);
    float inv = 1.f / sum;
    #pragma unroll
    for (int i = 0; i < 10; i++) {
        int m = lane + 32 * i;
        rp[m] = __float2half_rn((m < Mkv) ? v[i] * inv : 0.f);
    }
}

// ---------------------------------------------------------------------------
__global__ __launch_bounds__(256)
void dwglu_kernel(const __half* __restrict__ h, const float* __restrict__ dww,
                  const float* __restrict__ dwb, __half* __restrict__ out)
{
    __shared__ float sa[100][64];
    __shared__ float sg[100][64];
    int tid = threadIdx.x;
    int c0  = blockIdx.x * 64;
    int y0  = (blockIdx.y >> 3) * 8, x0 = (blockIdx.y & 7) * 8;
    int b   = blockIdx.z;

    int ch = tid & 63;
    float wA[9], wG[9];
    #pragma unroll
    for (int tp = 0; tp < 9; tp++) {
        wA[tp] = dww[(size_t)(c0 + ch) * 9 + tp];
        wG[tp] = dww[(size_t)(c0 + ch + HIDd) * 9 + tp];
    }
    float bA = dwb[c0 + ch], bG = dwb[c0 + ch + HIDd];

    for (int li = tid; li < 1600; li += 256) {
        int pos = li >> 4, q = li & 15;
        int py = pos / 10, px = pos % 10;
        int yy = y0 + py - 1, xx = x0 + px - 1;
        float4 va = make_float4(0.f, 0.f, 0.f, 0.f), vg = va;
        if (yy >= 0 && yy < 64 && xx >= 0 && xx < 64) {
            const __half* src = h + ((size_t)b * Nn + yy * 64 + xx) * (2 * HIDd) + c0 + q * 4;
            float2 a01 = __half22float2(*(const __half2*)src);
            float2 a23 = __half22float2(*(const __half2*)(src + 2));
            float2 g01 = __half22float2(*(const __half2*)(src + HIDd));
            float2 g23 = __half22float2(*(const __half2*)(src + HIDd + 2));
            va = make_float4(a01.x, a01.y, a23.x, a23.y);
            vg = make_float4(g01.x, g01.y, g23.x, g23.y);
        }
        *(float4*)&sa[pos][q * 4] = va;
        *(float4*)&sg[pos][q * 4] = vg;
    }
    __syncthreads();

    #pragma unroll
    for (int i = 0; i < 16; i++) {
        int pos = (tid >> 6) + i * 4;
        int py = pos >> 3, px = pos & 7;
        int s0 = (py + 1) * 10 + (px + 1);
        float accA = bA, accG = bG;
        #pragma unroll
        for (int dy = -1; dy <= 1; dy++)
            #pragma unroll
            for (int dx = -1; dx <= 1; dx++) {
                int s = s0 + dy * 10 + dx;
                int tp = (dy + 1) * 3 + (dx + 1);
                accA = fmaf(sa[s][ch], wA[tp], accA);
                accG = fmaf(sg[s][ch], wG[tp], accG);
            }
        int n = (y0 + py) * 64 + (x0 + px);
        out[((size_t)b * Nn + n) * HIDd + c0 + ch] =
            __float2half_rn(accA * fsilu(accG));
    }
}

// ---------------------------------------------------------------------------
extern "C" void kernel_launch(void* const* d_in, const int* /*in_sizes*/, int /*n_in*/,
                              void* d_out, int /*out_size*/)
{
    const float* x       = (const float*)d_in[0];
    const float* y       = (const float*)d_in[1];
    const float* t       = (const float*)d_in[2];
    const float* sst     = (const float*)d_in[3];
    const float* qkv_w   = (const float*)d_in[4];
    const float* aproj_w = (const float*)d_in[5];
    const float* aproj_b = (const float*)d_in[6];
    const float* q_w     = (const float*)d_in[7];
    const float* q_b     = (const float*)d_in[8];
    const float* kv_w    = (const float*)d_in[9];
    const float* kv_b    = (const float*)d_in[10];
    const float* cproj_w = (const float*)d_in[11];
    const float* cproj_b = (const float*)d_in[12];
    const float* inv_w   = (const float*)d_in[13];
    const float* inv_b   = (const float*)d_in[14];
    const float* dw_w    = (const float*)d_in[15];
    const float* dw_b    = (const float*)d_in[16];
    const float* pw_w    = (const float*)d_in[17];
    float* out = (float*)d_out;

    float  *p_big, *p_x1, *p_x2, *p_vk, *p_m;
    __half *p_shh, *p_x1h, *p_glu, *p_kvh, *p_vt, *p_prb, *p_yh, *p_w;
    cudaGetSymbolAddress((void**)&p_big, g_big);
    cudaGetSymbolAddress((void**)&p_shh, g_shh);
    cudaGetSymbolAddress((void**)&p_x1,  g_x1);
    cudaGetSymbolAddress((void**)&p_x1h, g_x1h);
    cudaGetSymbolAddress((void**)&p_x2,  g_x2);
    cudaGetSymbolAddress((void**)&p_glu, g_glu);
    cudaGetSymbolAddress((void**)&p_kvh, g_kvb);
    cudaGetSymbolAddress((void**)&p_vt,  g_vt);
    cudaGetSymbolAddress((void**)&p_prb, g_prb);
    cudaGetSymbolAddress((void**)&p_yh,  g_yh);
    cudaGetSymbolAddress((void**)&p_vk,  g_vk);
    cudaGetSymbolAddress((void**)&p_m,   g_mb);
    cudaGetSymbolAddress((void**)&p_w,   g_wts);

    __half* p_bigh = (__half*)p_big;

    cudaFuncSetAttribute(mma_gemm<false,0,false,true ,64,false>, cudaFuncAttributeMaxDynamicSharedMemorySize, MM_SMEM64);
    cudaFuncSetAttribute(mma_gemm<true ,3,true ,true ,64,false>, cudaFuncAttributeMaxDynamicSharedMemorySize, MM_SMEM64);
    cudaFuncSetAttribute(mma_gemm<true ,0,false,true ,64,false>, cudaFuncAttributeMaxDynamicSharedMemorySize, MM_SMEM64);
    cudaFuncSetAttribute(mma_gemm<true ,0,false,true ,64,true >, cudaFuncAttributeMaxDynamicSharedMemorySize, MM_SMEM64);
    cudaFuncSetAttribute(mma_gemm<false,0,true ,false,32,false>, cudaFuncAttributeMaxDynamicSharedMemorySize, MM_SMEM32);
    cudaFuncSetAttribute(mma_gemm<true ,2,true ,false,64,false>, cudaFuncAttributeMaxDynamicSharedMemorySize, MM_SMEM64);
    cudaFuncSetAttribute(mma_gemm<true ,1,false,true ,64,false>, cudaFuncAttributeMaxDynamicSharedMemorySize, MM_SMEM64);
    cudaFuncSetAttribute(mma_gemm<false,3,true ,false,64,false>, cudaFuncAttributeMaxDynamicSharedMemorySize, MM_SMEM64);

    const int ROWS = Bb * Nn;
    const long RN_TOTAL = (long)3*Cc*Cc + 5L*Cc*Cc + 2L*HIDd*Cc + (long)Cc*HIDd
                        + (long)Bb*Mkv*Cc + (long)Bb*6*Cc
                        + (long)Bb*HLA*33*32 + (long)Bb*HX*72*SLD;

    round_all_kernel<<<(int)((RN_TOTAL + 255) / 256), 256>>>(
        qkv_w, aproj_w, q_w, kv_w, cproj_w, inv_w, pw_w, y, t, sst);
    ln_mod_kernel<<<ROWS, 256>>>(x, p_shh, 1, 0);

    // qkv = xmod1 @ qkv_w.T
    mma_gemm<false,0,false,true,64,false><<<dim3(27, 64), 256, MM_SMEM64>>>(
        p_shh, p_w + W_QKV, nullptr, nullptr, nullptr, nullptr, p_bigh, nullptr,
        ROWS, 3 * Cc, 3 * Cc, Cc, Cc, Cc, 3 * Cc,
        1, 0, 0, 0, 0, 0, 0, 0);

    vk_kernel<<<dim3(Bb * HLA, 32), 352>>>(p_bigh, p_vk);
    la_out_kernel<<<ROWS / 4, 256>>>(p_bigh, p_vk, p_shh);

    // x1 = x + g_a * (la @ aproj_w.T + b)
    mma_gemm<true,3,true,true,64,false><<<dim3(9, 64), 256, MM_SMEM64>>>(
        p_shh, p_w + W_APR, aproj_b, x, p_m + 2 * Cc, p_x1, p_x1h, nullptr,
        ROWS, Cc, Cc, Cc, Cc, Cc, Cc,
        1, 0, 0, 0, 0, 0, 0, 6 * Cc);

    // q = x1 @ q_w.T + q_b
    mma_gemm<true,0,false,true,64,false><<<dim3(9, 64), 256, MM_SMEM64>>>(
        p_x1h, p_w + W_Q, q_b, nullptr, nullptr, nullptr, p_shh, nullptr,
        ROWS, Cc, Cc, Cc, Cc, Cc, Cc,
        1, 0, 0, 0, 0, 0, 0, 0);

    // kv = y @ kv_w.T + kv_b  (+ fused v^T scatter)
    mma_gemm<true,0,false,true,64,true><<<dim3(18, 5), 256, MM_SMEM64>>>(
        p_yh, p_w + W_KV, kv_b, nullptr, nullptr, nullptr, p_kvh, p_vt,
        Bb * Mkv, 2 * Cc, 2 * Cc, Cc, Cc, Cc, 2 * Cc,
        1, 0, 0, 0, 0, 0, 0, 0);

    // scores[z] = q_h @ k_h.T  (BK=32; store only the 300 real cols)
    mma_gemm<false,0,true,false,32,false><<<dim3(3, 32, Bb * HX), 256, MM_SMEM32>>>(
        p_shh, p_kvh, nullptr, nullptr, nullptr, p_big, nullptr, nullptr,
        Nn, Mkv, Mkv, 72, Cc, 2 * Cc, SLD,
        HX, (long)Nn * Cc, 72, (long)Mkv * 2 * Cc, 72,
        (long)HX * Nn * SLD, (long)Nn * SLD, 0);

    softmax_kernel<<<(Bb * HX * Nn) / 8, 256>>>(p_big, p_prb, (long)Bb * HX * Nn);

    // o[z] = probs @ v^T
    mma_gemm<false,0,false,true,64,false><<<dim3(1, 32, Bb * HX), 256, MM_SMEM64>>>(
        p_prb, p_vt, nullptr, nullptr, nullptr, nullptr, p_shh, nullptr,
        Nn, 72, 72, SLD, SLD, SLD, Cc,
        HX, (long)HX * Nn * SLD, (long)Nn * SLD, (long)72 * SLD * HX, (long)72 * SLD,
        (long)Nn * Cc, 72, 0);

    // x2 = x1 + o @ cproj_w.T + b
    mma_gemm<true,2,true,false,64,false><<<dim3(9, 64), 256, MM_SMEM64>>>(
        p_shh, p_w + W_CPR, cproj_b, p_x1, nullptr, p_x2, nullptr, nullptr,
        ROWS, Cc, Cc, Cc, Cc, Cc, Cc,
        1, 0, 0, 0, 0, 0, 0, 0);

    ln_mod_kernel<<<ROWS, 256>>>(p_x2, p_shh, 4, 3);

    // h = silu(xmod2 @ inv_w.T + b)
    mma_gemm<true,1,false,true,64,false><<<dim3(45, 64), 256, MM_SMEM64>>>(
        p_shh, p_w + W_INV, inv_b, nullptr, nullptr, nullptr, p_bigh, nullptr,
        ROWS, 2 * HIDd, 2 * HIDd, Cc, Cc, Cc, 2 * HIDd,
        1, 0, 0, 0, 0, 0, 0, 0);

    dwglu_kernel<<<dim3(HIDd / 64, 64, Bb), 256>>>(p_bigh, dw_w, dw_b, p_glu);

    // out = x2 + g_m * (glu @ pw_w.T)
    mma_gemm<false,3,true,false,64,false><<<dim3(9, 64), 256, MM_SMEM64>>>(
        p_glu, p_w + W_PW, nullptr, p_x2, p_m + 5 * Cc, out, nullptr, nullptr,
        ROWS, Cc, Cc, HIDd, HIDd, HIDd, Cc,
        1, 0, 0, 0, 0, 0, 0, 6 * Cc);
}

// round 17
// speedup vs baseline: 1.0157x; 1.0141x over previous
#include <cuda_runtime.h>
#include <cuda_fp16.h>
#include <cstdint>
#include <math.h>

// ---------------------------------------------------------------------------
// SanaBlock: LN+adaLN -> LiteLA -> cross-attn -> GLUMBConv, B=2,N=4096,C=1152
// R17: vectorized smem staging in vk (uint2->float4, no pad) and la_out
//      (half2). Everything else as R16.
// ---------------------------------------------------------------------------
constexpr int Bb   = 2;
constexpr int Nn   = 4096;
constexpr int Cc   = 1152;
constexpr int Mkv  = 300;
constexpr int HIDd = 2880;
constexpr int HLA  = 36;
constexpr int HX   = 16;
constexpr int SLD  = 320;

__device__ __align__(256) float  g_big [47185920];
__device__ __align__(256) __half g_shh [(size_t)Bb * Nn * Cc];
__device__ __align__(256) float  g_x1  [(size_t)Bb * Nn * Cc];
__device__ __align__(256) __half g_x1h [(size_t)Bb * Nn * Cc];
__device__ __align__(256) float  g_x2  [(size_t)Bb * Nn * Cc];
__device__ __align__(256) __half g_glu [(size_t)Bb * Nn * HIDd];
__device__ __align__(256) __half g_kvb [(size_t)Bb * Mkv * 2 * Cc];
__device__ __align__(256) __half g_vt  [(size_t)Bb * HX * 72 * SLD];
__device__ __align__(256) __half g_prb [(size_t)Bb * HX * Nn * SLD];
__device__ __align__(256) __half g_yh  [(size_t)Bb * Mkv * Cc];
__device__ __align__(256) __half g_wts [20570112];
__device__ float g_vk [Bb * HLA * 33 * 32];   // transposed: [bh][d:32][e:33]
__device__ float g_mb [Bb * 6 * Cc];

constexpr size_t W_QKV = 0;
constexpr size_t W_APR = W_QKV + (size_t)3 * Cc * Cc;
constexpr size_t W_Q   = W_APR + (size_t)Cc * Cc;
constexpr size_t W_KV  = W_Q   + (size_t)Cc * Cc;
constexpr size_t W_CPR = W_KV  + (size_t)2 * Cc * Cc;
constexpr size_t W_INV = W_CPR + (size_t)Cc * Cc;
constexpr size_t W_PW  = W_INV + (size_t)2 * HIDd * Cc;

// ---------------------------------------------------------------------------
// FMA-only transcendentals
// ---------------------------------------------------------------------------
__device__ __forceinline__ float fexp(float t){
    t = fminf(fmaxf(t, -87.0f), 87.0f);
    float z = t * 1.4426950408889634f;
    float n = floorf(z);
    float f = z - n;
    float p = 1.5403530e-4f;
    p = fmaf(p, f, 1.3333558e-3f);
    p = fmaf(p, f, 9.6181291e-3f);
    p = fmaf(p, f, 5.5504109e-2f);
    p = fmaf(p, f, 2.4022651e-1f);
    p = fmaf(p, f, 6.9314718e-1f);
    p = fmaf(p, f, 1.0f);
    int i = (int)n;
    return p * __int_as_float((i + 127) << 23);
}
__device__ __forceinline__ float fsigmoid(float x){
    float u = fexp(-fabsf(x));
    float z = 1.0f + u;                    // [1,2]
    float y = fmaf(-0.47058824f, z, 1.4117647f);
    y = y * fmaf(-z, y, 2.0f);
    y = y * fmaf(-z, y, 2.0f);
    return (x >= 0.f) ? y : 1.0f - y;
}
__device__ __forceinline__ float fsilu(float x){ return x * fsigmoid(x); }

// ---------------------------------------------------------------------------
// helpers
// ---------------------------------------------------------------------------
__device__ __forceinline__ uint32_t smem_u32(const void* p){
    uint32_t a;
    asm("{ .reg .u64 t; cvta.to.shared.u64 t, %1; cvt.u32.u64 %0, t; }"
        : "=r"(a) : "l"(p));
    return a;
}
__device__ __forceinline__ void cp16(uint32_t dst, const void* src, int srcsz){
    asm volatile("cp.async.cg.shared.global [%0], [%1], 16, %2;"
        ::"r"(dst),"l"(src),"r"(srcsz):"memory");
}
#define CP_COMMIT() asm volatile("cp.async.commit_group;":::"memory")
#define CP_WAIT1()  asm volatile("cp.async.wait_group 1;":::"memory")

__device__ __forceinline__ void mma16(float* d, const uint32_t* a, const uint32_t* b){
    asm volatile("mma.sync.aligned.m16n8k16.row.col.f32.f16.f16.f32 "
        "{%0,%1,%2,%3},{%4,%5,%6,%7},{%8,%9},{%0,%1,%2,%3};"
        : "+f"(d[0]),"+f"(d[1]),"+f"(d[2]),"+f"(d[3])
        : "r"(a[0]),"r"(a[1]),"r"(a[2]),"r"(a[3]),"r"(b[0]),"r"(b[1]));
}
__device__ __forceinline__ void ldsm4(uint32_t& r0, uint32_t& r1, uint32_t& r2,
                                      uint32_t& r3, uint32_t addr){
    asm volatile("ldmatrix.sync.aligned.m8n8.x4.shared.b16 {%0,%1,%2,%3}, [%4];"
        : "=r"(r0),"=r"(r1),"=r"(r2),"=r"(r3) : "r"(addr));
}

// ---------------------------------------------------------------------------
// fp16 mma NT GEMM, BK templated (32 or 64): 3-stage cp.async, 1 barrier/tile.
// CTA 128x128, 8 warps (4M x 2N), warp tile 32x64, ldmatrix.x4 fragments.
// VT: scatter v-half of kv output into g_vt (transposed, padded).
// ---------------------------------------------------------------------------
template<int BK> struct GK {
    static constexpr int LDPH    = BK + 8;
    static constexpr int TILE_H  = 128 * LDPH;
    static constexpr int STAGE_H = 2 * TILE_H;
    static constexpr int SMEM    = 3 * STAGE_H * 2;
};
constexpr int MM_SMEM64 = GK<64>::SMEM;   // 110592
constexpr int MM_SMEM32 = GK<32>::SMEM;   // 61440

template<bool BIAS, int EPI, bool WF, bool WH, int BK, bool VT>
__global__ __launch_bounds__(256, 2)
void mma_gemm(const __half* A, const __half* Bw, const float* bias,
              const float* res, const float* gate,
              float* Of, __half* Oh, __half* vtout,
              int Mrows, int NloadB, int Nstore, int K,
              int lda, int ldb, int ldo,
              int HB, long aBs, long aHs, long bBs, long bHs, long oBs, long oHs,
              int gateStride)
{
    constexpr int LDPH    = GK<BK>::LDPH;
    constexpr int TILE_H  = GK<BK>::TILE_H;
    constexpr int STAGE_H = GK<BK>::STAGE_H;
    constexpr int CPR     = BK / 8;
    constexpr int LITER   = BK / 16;

    extern __shared__ __half smh[];
    uint32_t sbase = smem_u32(smh);
    int tid = threadIdx.x, wid = tid >> 5, lane = tid & 31;
    int warpM = wid >> 1, warpN = wid & 1;
    int m0 = blockIdx.y * 128, n0 = blockIdx.x * 128;

    if (gridDim.z > 1) {
        int z = blockIdx.z;
        int bI = z / HB, hI = z % HB;
        A  += bI * aBs + hI * aHs;
        Bw += bI * bBs + hI * bHs;
        if (WF) Of += bI * oBs + hI * oHs;
        if (WH) Oh += bI * oBs + hI * oHs;
    }

    const int T = (K + BK - 1) / BK;

    auto load_tile = [&](int t, int buf) {
        uint32_t base = sbase + (uint32_t)buf * STAGE_H * 2;
        int k0 = t * BK;
        #pragma unroll
        for (int i = 0; i < LITER; i++) {
            int c = tid + (i << 8);
            int row = c / CPR, ch = c % CPR;
            int gk = k0 + ch * 8;
            uint32_t dst = base + (uint32_t)(row * LDPH + ch * 8) * 2;
            const __half* ga = A + (size_t)(m0 + row) * lda + gk;
            cp16(dst, ga, ((m0 + row) < Mrows && gk < K) ? 16 : 0);
        }
        #pragma unroll
        for (int i = 0; i < LITER; i++) {
            int c = tid + (i << 8);
            int row = c / CPR, ch = c % CPR;
            int gk = k0 + ch * 8;
            uint32_t dst = base + (uint32_t)(TILE_H + row * LDPH + ch * 8) * 2;
            const __half* gb = Bw + (size_t)(n0 + row) * ldb + gk;
            cp16(dst, gb, ((n0 + row) < NloadB && gk < K) ? 16 : 0);
        }
    };

    float acc[2][8][4];
    #pragma unroll
    for (int mt = 0; mt < 2; mt++)
        #pragma unroll
        for (int nt = 0; nt < 8; nt++)
            #pragma unroll
            for (int q = 0; q < 4; q++) acc[mt][nt][q] = 0.f;

    load_tile(0, 0); CP_COMMIT();
    load_tile(1, 1); CP_COMMIT();

    int rowA = warpM * 32 + (lane & 15);
    int colA = (lane >> 4) << 3;
    int rowB = warpN * 64 + (lane & 7) + ((lane >> 4) << 3);
    int colB = ((lane >> 3) & 1) << 3;
    uint32_t offA = (uint32_t)(rowA * LDPH + colA) * 2;
    uint32_t offB = (uint32_t)(TILE_H + rowB * LDPH + colB) * 2;

    for (int t = 0; t < T; t++) {
        int buf = t % 3;
        CP_WAIT1();
        __syncthreads();
        if (t + 2 < T) load_tile(t + 2, (t + 2) % 3);
        CP_COMMIT();

        uint32_t sA = sbase + (uint32_t)buf * STAGE_H * 2;

        #pragma unroll
        for (int kk = 0; kk < BK / 16; kk++) {
            uint32_t af[2][4];
            #pragma unroll
            for (int mt = 0; mt < 2; mt++) {
                uint32_t addr = sA + offA + (uint32_t)(mt * 16 * LDPH + kk * 16) * 2;
                ldsm4(af[mt][0], af[mt][1], af[mt][2], af[mt][3], addr);
            }
            uint32_t bf[8][2];
            #pragma unroll
            for (int ntp = 0; ntp < 4; ntp++) {
                uint32_t addr = sA + offB + (uint32_t)(ntp * 16 * LDPH + kk * 16) * 2;
                ldsm4(bf[2 * ntp][0], bf[2 * ntp][1],
                      bf[2 * ntp + 1][0], bf[2 * ntp + 1][1], addr);
            }
            #pragma unroll
            for (int mt = 0; mt < 2; mt++)
                #pragma unroll
                for (int nt = 0; nt < 8; nt++)
                    mma16(acc[mt][nt], af[mt], bf[nt]);
        }
    }

    #pragma unroll
    for (int mt = 0; mt < 2; mt++) {
        #pragma unroll
        for (int half_ = 0; half_ < 2; half_++) {
            int row = m0 + warpM * 32 + mt * 16 + (lane >> 2) + half_ * 8;
            if (row >= Mrows) continue;
            int bI = (row >= Nn) ? 1 : 0;
            #pragma unroll
            for (int nt = 0; nt < 8; nt++) {
                int col = n0 + warpN * 64 + nt * 8 + (lane & 3) * 2;
                if (col >= Nstore) continue;
                float v0 = acc[mt][nt][half_ * 2];
                float v1 = acc[mt][nt][half_ * 2 + 1];
                if (BIAS) { v0 += bias[col]; v1 += bias[col + 1]; }
                if (EPI == 1) { v0 = fsilu(v0); v1 = fsilu(v1); }
                if (EPI == 2) {
                    v0 += res[(size_t)row * ldo + col];
                    v1 += res[(size_t)row * ldo + col + 1];
                }
                if (EPI == 3) {
                    v0 = res[(size_t)row * ldo + col]     + gate[bI * gateStride + col]     * v0;
                    v1 = res[(size_t)row * ldo + col + 1] + gate[bI * gateStride + col + 1] * v1;
                }
                if (WF) *(float2*)&Of[(size_t)row * ldo + col] = make_float2(v0, v1);
                if (WH) *(__half2*)&Oh[(size_t)row * ldo + col] = __floats2half2_rn(v0, v1);
                if (VT) {
                    if (col >= Cc) {
                        int bb = row / Mkv, m = row - bb * Mkv;
                        int hd = col - Cc;
                        int hh = hd / 72, dd = hd - hh * 72;
                        __half* vb = vtout + ((size_t)(bb * HX + hh) * 72 + dd) * SLD + m;
                        vb[0]   = __float2half_rn(v0);
                        vb[SLD] = __float2half_rn(v1);
                    }
                }
            }
        }
    }
}

// ---------------------------------------------------------------------------
// prologue: weight/y fp16 conversion + m=sst+t + vk zero + vt zero, ONE launch
// ---------------------------------------------------------------------------
__global__ void round_all_kernel(const float* qkv_w, const float* aproj_w,
                                 const float* q_w, const float* kv_w,
                                 const float* cproj_w, const float* inv_w,
                                 const float* pw_w, const float* y,
                                 const float* t, const float* sst)
{
    long i = (long)blockIdx.x * 256 + threadIdx.x;
    long n;
    n = (long)3 * Cc * Cc;   if (i < n) { g_wts[W_QKV + i] = __float2half_rn(qkv_w[i]);   return; } i -= n;
    n = (long)Cc * Cc;       if (i < n) { g_wts[W_APR + i] = __float2half_rn(aproj_w[i]); return; } i -= n;
    n = (long)Cc * Cc;       if (i < n) { g_wts[W_Q   + i] = __float2half_rn(q_w[i]);     return; } i -= n;
    n = (long)2 * Cc * Cc;   if (i < n) { g_wts[W_KV  + i] = __float2half_rn(kv_w[i]);    return; } i -= n;
    n = (long)Cc * Cc;       if (i < n) { g_wts[W_CPR + i] = __float2half_rn(cproj_w[i]); return; } i -= n;
    n = (long)2 * HIDd * Cc; if (i < n) { g_wts[W_INV + i] = __float2half_rn(inv_w[i]);   return; } i -= n;
    n = (long)Cc * HIDd;     if (i < n) { g_wts[W_PW  + i] = __float2half_rn(pw_w[i]);    return; } i -= n;
    n = (long)Bb * Mkv * Cc; if (i < n) { g_yh[i] = __float2half_rn(y[i]);                return; } i -= n;
    n = (long)Bb * 6 * Cc;   if (i < n) { g_mb[i] = sst[i % (6 * Cc)] + t[i];             return; } i -= n;
    n = (long)Bb * HLA * 33 * 32; if (i < n) { g_vk[i] = 0.f;                             return; } i -= n;
    n = (long)Bb * HX * 72 * SLD; if (i < n) { g_vt[i] = __float2half_rn(0.f); }
}

// ---------------------------------------------------------------------------
__global__ __launch_bounds__(256)
void ln_mod_kernel(const float* __restrict__ in, __half* __restrict__ out,
                   int scRow, int shRow)
{
    int row = blockIdx.x;
    int b   = row / Nn;
    const float* xr = in + (size_t)row * Cc;

    float s = 0.f, s2 = 0.f;
    for (int c = threadIdx.x; c < Cc; c += blockDim.x) {
        float v = xr[c]; s += v; s2 += v * v;
    }
    __shared__ float sh1[8], sh2[8];
    int lane = threadIdx.x & 31, wid = threadIdx.x >> 5;
    #pragma unroll
    for (int o = 16; o > 0; o >>= 1) {
        s  += __shfl_down_sync(0xffffffffu, s,  o);
        s2 += __shfl_down_sync(0xffffffffu, s2, o);
    }
    if (lane == 0) { sh1[wid] = s; sh2[wid] = s2; }
    __syncthreads();
    if (wid == 0) {
        s  = (lane < 8) ? sh1[lane] : 0.f;
        s2 = (lane < 8) ? sh2[lane] : 0.f;
        #pragma unroll
        for (int o = 4; o > 0; o >>= 1) {
            s  += __shfl_down_sync(0xffffffffu, s,  o);
            s2 += __shfl_down_sync(0xffffffffu, s2, o);
        }
        if (lane == 0) { sh1[0] = s; sh2[0] = s2; }
    }
    __syncthreads();
    float mu   = sh1[0] * (1.f / Cc);
    float var  = sh2[0] * (1.f / Cc) - mu * mu;
    float rstd = rsqrtf(var + 1e-6f);
    const float* mbp = g_mb + (size_t)b * 6 * Cc;
    for (int c = threadIdx.x; c < Cc; c += blockDim.x) {
        float sc = mbp[scRow * Cc + c];
        float sv = mbp[shRow * Cc + c];
        out[(size_t)row * Cc + c] =
            __float2half_rn((xr[c] - mu) * rstd * (1.f + sc) + sv);
    }
}

// ---------------------------------------------------------------------------
// LiteLA vk accumulation (transposed out): vectorized staging, no smem pad
// ---------------------------------------------------------------------------
__global__ __launch_bounds__(352)
void vk_kernel(const __half* __restrict__ qkv, float* __restrict__ vkout)
{
    int bh = blockIdx.x;
    int b  = bh / HLA, h = bh % HLA;
    int split = blockIdx.y;
    __shared__ float ks[32][32];
    __shared__ float vs[32][32];
    float acc[3] = {0.f, 0.f, 0.f};
    int tid = threadIdx.x;
    const size_t base = (size_t)b * Nn * 3 * Cc + h * 32;
    int nStart = split * (Nn / 32);
    for (int n0 = nStart; n0 < nStart + Nn / 32; n0 += 32) {
        if (tid < 256) {
            int nn = tid >> 3, dc4 = (tid & 7) * 4;
            size_t off = base + (size_t)(n0 + nn) * 3 * Cc + dc4;
            uint2 kr = *(const uint2*)(qkv + off + Cc);
            uint2 vr = *(const uint2*)(qkv + off + 2 * Cc);
            float2 k01 = __half22float2(*(__half2*)&kr.x);
            float2 k23 = __half22float2(*(__half2*)&kr.y);
            float2 v01 = __half22float2(*(__half2*)&vr.x);
            float2 v23 = __half22float2(*(__half2*)&vr.y);
            *(float4*)&ks[nn][dc4] = make_float4(
                fmaxf(k01.x, 0.f), fmaxf(k01.y, 0.f),
                fmaxf(k23.x, 0.f), fmaxf(k23.y, 0.f));
            *(float4*)&vs[nn][dc4] = make_float4(v01.x, v01.y, v23.x, v23.y);
        }
        __syncthreads();
        #pragma unroll
        for (int u = 0; u < 3; u++) {
            int idx = tid + 352 * u;             // 0..1055 exact
            int e = idx >> 5, dc = idx & 31;
            float a = acc[u];
            if (e == 32) {
                #pragma unroll
                for (int nn = 0; nn < 32; nn++) a += ks[nn][dc];
            } else {
                #pragma unroll
                for (int nn = 0; nn < 32; nn++) a += vs[nn][e] * ks[nn][dc];
            }
            acc[u] = a;
        }
        __syncthreads();
    }
    #pragma unroll
    for (int u = 0; u < 3; u++) {
        int idx = tid + 352 * u;
        int e = idx >> 5, dc = idx & 31;
        atomicAdd(&vkout[((size_t)bh * 32 + dc) * 33 + e], acc[u]);
    }
}

// ---------------------------------------------------------------------------
// la_out: 4 rows per CTA; half2 q staging; vk col in regs reused across rows
// ---------------------------------------------------------------------------
__global__ __launch_bounds__(256)
void la_out_kernel(const __half* __restrict__ qkv, const float* __restrict__ vk,
                   __half* __restrict__ out)
{
    int row0 = blockIdx.x * 4;
    int b    = row0 / Nn;                  // Nn % 4 == 0: no straddle
    __shared__ float q[4][Cc];
    __shared__ float rden[4][HLA];

    for (int i = threadIdx.x; i < 4 * (Cc / 2); i += 256) {
        int r = i / (Cc / 2), c2 = i - r * (Cc / 2);
        __half2 hv = *(const __half2*)(qkv + (size_t)(row0 + r) * 3 * Cc + c2 * 2);
        float2 fv = __half22float2(hv);
        q[r][c2 * 2]     = fmaxf(fv.x, 0.f);
        q[r][c2 * 2 + 1] = fmaxf(fv.y, 0.f);
    }
    __syncthreads();

    if (threadIdx.x < 4 * HLA) {
        int r = threadIdx.x / HLA, h = threadIdx.x - r * HLA;
        const float* vkh = vk + (size_t)(b * HLA + h) * 32 * 33;
        float s = 0.f;
        #pragma unroll
        for (int d = 0; d < 32; d++) s += vkh[d * 33 + 32] * q[r][h * 32 + d];
        rden[r][h] = 1.0f / (s + 1e-8f);
    }
    __syncthreads();

    for (int c = threadIdx.x; c < Cc; c += 256) {
        int h = c >> 5, dd = c & 31;
        const float* vkr = vk + (size_t)(b * HLA + h) * 32 * 33 + dd;
        float vreg[32];
        #pragma unroll
        for (int d = 0; d < 32; d++) vreg[d] = vkr[d * 33];
        #pragma unroll
        for (int r = 0; r < 4; r++) {
            const float* qh = &q[r][h * 32];
            float s = 0.f;
            #pragma unroll
            for (int d = 0; d < 32; d++) s += vreg[d] * qh[d];
            out[(size_t)(row0 + r) * Cc + c] = __float2half_rn(s * rden[r][h]);
        }
    }
}

// ---------------------------------------------------------------------------
__global__ __launch_bounds__(256)
void softmax_kernel(const float* __restrict__ s, __half* __restrict__ p, long rows)
{
    long gw  = ((long)blockIdx.x * blockDim.x + threadIdx.x) >> 5;
    int lane = threadIdx.x & 31;
    if (gw >= rows) return;
    const float* r = s + gw * SLD;
    __half* rp = p + gw * SLD;
    const float scale = 0.11785113019775793f;
    float v[10];
    float mx = -1e30f;
    #pragma unroll
    for (int i = 0; i < 10; i++) {
        int m = lane + 32 * i;
        v[i] = (m < Mkv) ? r[m] * scale : -1e30f;
        mx = fmaxf(mx, v[i]);
    }
    #pragma unroll
    for (int o = 16; o > 0; o >>= 1) mx = fmaxf(mx, __shfl_xor_sync(0xffffffffu, mx, o));
    float sum = 0.f;
    #pragma unroll
    for (int i = 0; i < 10; i++) { v[i] = fexp(v[i] - mx); sum += v[i]; }
    #pragma unroll
    for (int o = 16; o > 0; o >>= 1) sum += __shfl_xor_sync(0xffffffffu, sum, o);
    float inv = 1.f / sum;
    #pragma unroll
    for (int i = 0; i < 10; i++) {
        int m = lane + 32 * i;
        rp[m] = __float2half_rn((m < Mkv) ? v[i] * inv : 0.f);
    }
}

// ---------------------------------------------------------------------------
__global__ __launch_bounds__(256)
void dwglu_kernel(const __half* __restrict__ h, const float* __restrict__ dww,
                  const float* __restrict__ dwb, __half* __restrict__ out)
{
    __shared__ float sa[100][64];
    __shared__ float sg[100][64];
    int tid = threadIdx.x;
    int c0  = blockIdx.x * 64;
    int y0  = (blockIdx.y >> 3) * 8, x0 = (blockIdx.y & 7) * 8;
    int b   = blockIdx.z;

    int ch = tid & 63;
    float wA[9], wG[9];
    #pragma unroll
    for (int tp = 0; tp < 9; tp++) {
        wA[tp] = dww[(size_t)(c0 + ch) * 9 + tp];
        wG[tp] = dww[(size_t)(c0 + ch + HIDd) * 9 + tp];
    }
    float bA = dwb[c0 + ch], bG = dwb[c0 + ch + HIDd];

    for (int li = tid; li < 1600; li += 256) {
        int pos = li >> 4, q = li & 15;
        int py = pos / 10, px = pos % 10;
        int yy = y0 + py - 1, xx = x0 + px - 1;
        float4 va = make_float4(0.f, 0.f, 0.f, 0.f), vg = va;
        if (yy >= 0 && yy < 64 && xx >= 0 && xx < 64) {
            const __half* src = h + ((size_t)b * Nn + yy * 64 + xx) * (2 * HIDd) + c0 + q * 4;
            float2 a01 = __half22float2(*(const __half2*)src);
            float2 a23 = __half22float2(*(const __half2*)(src + 2));
            float2 g01 = __half22float2(*(const __half2*)(src + HIDd));
            float2 g23 = __half22float2(*(const __half2*)(src + HIDd + 2));
            va = make_float4(a01.x, a01.y, a23.x, a23.y);
            vg = make_float4(g01.x, g01.y, g23.x, g23.y);
        }
        *(float4*)&sa[pos][q * 4] = va;
        *(float4*)&sg[pos][q * 4] = vg;
    }
    __syncthreads();

    #pragma unroll
    for (int i = 0; i < 16; i++) {
        int pos = (tid >> 6) + i * 4;
        int py = pos >> 3, px = pos & 7;
        int s0 = (py + 1) * 10 + (px + 1);
        float accA = bA, accG = bG;
        #pragma unroll
        for (int dy = -1; dy <= 1; dy++)
            #pragma unroll
            for (int dx = -1; dx <= 1; dx++) {
                int s = s0 + dy * 10 + dx;
                int tp = (dy + 1) * 3 + (dx + 1);
                accA = fmaf(sa[s][ch], wA[tp], accA);
                accG = fmaf(sg[s][ch], wG[tp], accG);
            }
        int n = (y0 + py) * 64 + (x0 + px);
        out[((size_t)b * Nn + n) * HIDd + c0 + ch] =
            __float2half_rn(accA * fsilu(accG));
    }
}

// ---------------------------------------------------------------------------
extern "C" void kernel_launch(void* const* d_in, const int* /*in_sizes*/, int /*n_in*/,
                              void* d_out, int /*out_size*/)
{
    const float* x       = (const float*)d_in[0];
    const float* y       = (const float*)d_in[1];
    const float* t       = (const float*)d_in[2];
    const float* sst     = (const float*)d_in[3];
    const float* qkv_w   = (const float*)d_in[4];
    const float* aproj_w = (const float*)d_in[5];
    const float* aproj_b = (const float*)d_in[6];
    const float* q_w     = (const float*)d_in[7];
    const float* q_b     = (const float*)d_in[8];
    const float* kv_w    = (const float*)d_in[9];
    const float* kv_b    = (const float*)d_in[10];
    const float* cproj_w = (const float*)d_in[11];
    const float* cproj_b = (const float*)d_in[12];
    const float* inv_w   = (const float*)d_in[13];
    const float* inv_b   = (const float*)d_in[14];
    const float* dw_w    = (const float*)d_in[15];
    const float* dw_b    = (const float*)d_in[16];
    const float* pw_w    = (const float*)d_in[17];
    float* out = (float*)d_out;

    float  *p_big, *p_x1, *p_x2, *p_vk, *p_m;
    __half *p_shh, *p_x1h, *p_glu, *p_kvh, *p_vt, *p_prb, *p_yh, *p_w;
    cudaGetSymbolAddress((void**)&p_big, g_big);
    cudaGetSymbolAddress((void**)&p_shh, g_shh);
    cudaGetSymbolAddress((void**)&p_x1,  g_x1);
    cudaGetSymbolAddress((void**)&p_x1h, g_x1h);
    cudaGetSymbolAddress((void**)&p_x2,  g_x2);
    cudaGetSymbolAddress((void**)&p_glu, g_glu);
    cudaGetSymbolAddress((void**)&p_kvh, g_kvb);
    cudaGetSymbolAddress((void**)&p_vt,  g_vt);
    cudaGetSymbolAddress((void**)&p_prb, g_prb);
    cudaGetSymbolAddress((void**)&p_yh,  g_yh);
    cudaGetSymbolAddress((void**)&p_vk,  g_vk);
    cudaGetSymbolAddress((void**)&p_m,   g_mb);
    cudaGetSymbolAddress((void**)&p_w,   g_wts);

    __half* p_bigh = (__half*)p_big;

    cudaFuncSetAttribute(mma_gemm<false,0,false,true ,64,false>, cudaFuncAttributeMaxDynamicSharedMemorySize, MM_SMEM64);
    cudaFuncSetAttribute(mma_gemm<true ,3,true ,true ,64,false>, cudaFuncAttributeMaxDynamicSharedMemorySize, MM_SMEM64);
    cudaFuncSetAttribute(mma_gemm<true ,0,false,true ,64,false>, cudaFuncAttributeMaxDynamicSharedMemorySize, MM_SMEM64);
    cudaFuncSetAttribute(mma_gemm<true ,0,false,true ,64,true >, cudaFuncAttributeMaxDynamicSharedMemorySize, MM_SMEM64);
    cudaFuncSetAttribute(mma_gemm<false,0,true ,false,32,false>, cudaFuncAttributeMaxDynamicSharedMemorySize, MM_SMEM32);
    cudaFuncSetAttribute(mma_gemm<true ,2,true ,false,64,false>, cudaFuncAttributeMaxDynamicSharedMemorySize, MM_SMEM64);
    cudaFuncSetAttribute(mma_gemm<true ,1,false,true ,64,false>, cudaFuncAttributeMaxDynamicSharedMemorySize, MM_SMEM64);
    cudaFuncSetAttribute(mma_gemm<false,3,true ,false,64,false>, cudaFuncAttributeMaxDynamicSharedMemorySize, MM_SMEM64);

    const int ROWS = Bb * Nn;
    const long RN_TOTAL = (long)3*Cc*Cc + 5L*Cc*Cc + 2L*HIDd*Cc + (long)Cc*HIDd
                        + (long)Bb*Mkv*Cc + (long)Bb*6*Cc
                        + (long)Bb*HLA*33*32 + (long)Bb*HX*72*SLD;

    round_all_kernel<<<(int)((RN_TOTAL + 255) / 256), 256>>>(
        qkv_w, aproj_w, q_w, kv_w, cproj_w, inv_w, pw_w, y, t, sst);
    ln_mod_kernel<<<ROWS, 256>>>(x, p_shh, 1, 0);

    // qkv = xmod1 @ qkv_w.T
    mma_gemm<false,0,false,true,64,false><<<dim3(27, 64), 256, MM_SMEM64>>>(
        p_shh, p_w + W_QKV, nullptr, nullptr, nullptr, nullptr, p_bigh, nullptr,
        ROWS, 3 * Cc, 3 * Cc, Cc, Cc, Cc, 3 * Cc,
        1, 0, 0, 0, 0, 0, 0, 0);

    vk_kernel<<<dim3(Bb * HLA, 32), 352>>>(p_bigh, p_vk);
    la_out_kernel<<<ROWS / 4, 256>>>(p_bigh, p_vk, p_shh);

    // x1 = x + g_a * (la @ aproj_w.T + b)
    mma_gemm<true,3,true,true,64,false><<<dim3(9, 64), 256, MM_SMEM64>>>(
        p_shh, p_w + W_APR, aproj_b, x, p_m + 2 * Cc, p_x1, p_x1h, nullptr,
        ROWS, Cc, Cc, Cc, Cc, Cc, Cc,
        1, 0, 0, 0, 0, 0, 0, 6 * Cc);

    // q = x1 @ q_w.T + q_b
    mma_gemm<true,0,false,true,64,false><<<dim3(9, 64), 256, MM_SMEM64>>>(
        p_x1h, p_w + W_Q, q_b, nullptr, nullptr, nullptr, p_shh, nullptr,
        ROWS, Cc, Cc, Cc, Cc, Cc, Cc,
        1, 0, 0, 0, 0, 0, 0, 0);

    // kv = y @ kv_w.T + kv_b  (+ fused v^T scatter)
    mma_gemm<true,0,false,true,64,true><<<dim3(18, 5), 256, MM_SMEM64>>>(
        p_yh, p_w + W_KV, kv_b, nullptr, nullptr, nullptr, p_kvh, p_vt,
        Bb * Mkv, 2 * Cc, 2 * Cc, Cc, Cc, Cc, 2 * Cc,
        1, 0, 0, 0, 0, 0, 0, 0);

    // scores[z] = q_h @ k_h.T  (BK=32; store only the 300 real cols)
    mma_gemm<false,0,true,false,32,false><<<dim3(3, 32, Bb * HX), 256, MM_SMEM32>>>(
        p_shh, p_kvh, nullptr, nullptr, nullptr, p_big, nullptr, nullptr,
        Nn, Mkv, Mkv, 72, Cc, 2 * Cc, SLD,
        HX, (long)Nn * Cc, 72, (long)Mkv * 2 * Cc, 72,
        (long)HX * Nn * SLD, (long)Nn * SLD, 0);

    softmax_kernel<<<(Bb * HX * Nn) / 8, 256>>>(p_big, p_prb, (long)Bb * HX * Nn);

    // o[z] = probs @ v^T
    mma_gemm<false,0,false,true,64,false><<<dim3(1, 32, Bb * HX), 256, MM_SMEM64>>>(
        p_prb, p_vt, nullptr, nullptr, nullptr, nullptr, p_shh, nullptr,
        Nn, 72, 72, SLD, SLD, SLD, Cc,
        HX, (long)HX * Nn * SLD, (long)Nn * SLD, (long)72 * SLD * HX, (long)72 * SLD,
        (long)Nn * Cc, 72, 0);

    // x2 = x1 + o @ cproj_w.T + b
    mma_gemm<true,2,true,false,64,false><<<dim3(9, 64), 256, MM_SMEM64>>>(
        p_shh, p_w + W_CPR, cproj_b, p_x1, nullptr, p_x2, nullptr, nullptr,
        ROWS, Cc, Cc, Cc, Cc, Cc, Cc,
        1, 0, 0, 0, 0, 0, 0, 0);

    ln_mod_kernel<<<ROWS, 256>>>(p_x2, p_shh, 4, 3);

    // h = silu(xmod2 @ inv_w.T + b)
    mma_gemm<true,1,false,true,64,false><<<dim3(45, 64), 256, MM_SMEM64>>>(
        p_shh, p_w + W_INV, inv_b, nullptr, nullptr, nullptr, p_bigh, nullptr,
        ROWS, 2 * HIDd, 2 * HIDd, Cc, Cc, Cc, 2 * HIDd,
        1, 0, 0, 0, 0, 0, 0, 0);

    dwglu_kernel<<<dim3(HIDd / 64, 64, Bb), 256>>>(p_bigh, dw_w, dw_b, p_glu);

    // out = x2 + g_m * (glu @ pw_w.T)
    mma_gemm<false,3,true,false,64,false><<<dim3(9, 64), 256, MM_SMEM64>>>(
        p_glu, p_w + W_PW, nullptr, p_x2, p_m + 5 * Cc, out, nullptr, nullptr,
        ROWS, Cc, Cc, HIDd, HIDd, HIDd, Cc,
        1, 0, 0, 0, 0, 0, 0, 6 * Cc);
}